// round 3
// baseline (speedup 1.0000x reference)
#include <cuda_runtime.h>
#include <cuda_bf16.h>
#include <cstdint>
#include <cstddef>

#define BB     8
#define TT     256
#define NEN    64
#define HH     512
#define HD     128
#define VOCAB  32000
#define NROWS  (BB*TT)
#define LDO    (VOCAB+NEN)

__device__ float g_K[BB*NEN*HH];
__device__ float g_V[BB*NEN*HH];
__device__ float g_hx[BB*HH];
__device__ float g_cx[BB*HH];
__device__ float g_a[BB*HH];
__device__ float g_l[(size_t)NROWS*2*HH];
__device__ float g_dec[(size_t)NROWS*HH];
__device__ float g_s[NROWS];
__device__ float g_rowsum[NROWS];
__device__ float g_c[NROWS];

__device__ __forceinline__ float sigf(float x) { return 1.0f / (1.0f + __expf(-x)); }

__device__ __forceinline__ float fexp(float x) {
    float z = x * 1.44269504088896f;
    float r = z + 12582912.0f;
    int   n = __float_as_int(r) - 0x4B400000;
    float f = z - (r - 12582912.0f);
    float p = 1.33336498e-3f;
    p = fmaf(p, f, 9.61011474e-3f);
    p = fmaf(p, f, 5.55036190e-2f);
    p = fmaf(p, f, 2.40226337e-1f);
    p = fmaf(p, f, 6.93147182e-1f);
    p = fmaf(p, f, 1.0f);
    return p * __int_as_float((n + 127) << 23);
}

__global__ void k_init(const float* __restrict__ ents) {
    int blk = blockIdx.x;
    if (blk < BB) {
        int b = blk, h = threadIdx.x;
        float s = 0.f;
        #pragma unroll 8
        for (int n = 0; n < NEN; n++) s += ents[(size_t)(b*NEN + n)*HH + h];
        s *= (1.0f / NEN);
        g_hx[b*HH + h] = s;
        g_cx[b*HH + h] = s;
        g_a [b*HH + h] = 0.f;
    } else {
        int i = (blk - BB)*512 + threadIdx.x;
        if (i < NROWS) g_rowsum[i] = 0.f;
    }
}

// C[M,N] = A[M,K]@Bm[N,K]^T + bias. 128x128 tile, 8x8/thread, K-step 16.
__global__ __launch_bounds__(256) void k_sgemm(
    const float* __restrict__ A, const float* __restrict__ Bm,
    const float* __restrict__ bias, float* __restrict__ C, int Kdim, int ldc)
{
    __shared__ float As[16][128];
    __shared__ float Bs[16][128];
    int m0 = blockIdx.y * 128, n0 = blockIdx.x * 128;
    int tid = threadIdx.x;
    int tx = tid & 15, ty = tid >> 4;
    int lr = tid >> 2, lc = tid & 3;
    float acc[8][8];
    #pragma unroll
    for (int i = 0; i < 8; i++)
        #pragma unroll
        for (int j = 0; j < 8; j++) acc[i][j] = 0.f;

    for (int k0 = 0; k0 < Kdim; k0 += 16) {
        #pragma unroll
        for (int i = 0; i < 2; i++) {
            float4 a4 = *(const float4*)&A[(size_t)(m0 + lr + 64*i)*Kdim + k0 + lc*4];
            As[lc*4+0][lr+64*i] = a4.x; As[lc*4+1][lr+64*i] = a4.y;
            As[lc*4+2][lr+64*i] = a4.z; As[lc*4+3][lr+64*i] = a4.w;
            float4 b4 = *(const float4*)&Bm[(size_t)(n0 + lr + 64*i)*Kdim + k0 + lc*4];
            Bs[lc*4+0][lr+64*i] = b4.x; Bs[lc*4+1][lr+64*i] = b4.y;
            Bs[lc*4+2][lr+64*i] = b4.z; Bs[lc*4+3][lr+64*i] = b4.w;
        }
        __syncthreads();
        #pragma unroll
        for (int kk = 0; kk < 16; kk++) {
            float a[8], b[8];
            *(float4*)&a[0] = *(const float4*)&As[kk][ty*8];
            *(float4*)&a[4] = *(const float4*)&As[kk][ty*8+4];
            *(float4*)&b[0] = *(const float4*)&Bs[kk][tx*8];
            *(float4*)&b[4] = *(const float4*)&Bs[kk][tx*8+4];
            #pragma unroll
            for (int i = 0; i < 8; i++)
                #pragma unroll
                for (int j = 0; j < 8; j++)
                    acc[i][j] = fmaf(a[i], b[j], acc[i][j]);
        }
        __syncthreads();
    }
    #pragma unroll
    for (int i = 0; i < 8; i++) {
        int m = m0 + ty*8 + i;
        #pragma unroll
        for (int jv = 0; jv < 2; jv++) {
            int n = n0 + tx*8 + jv*4;
            float4 v;
            v.x = acc[i][jv*4+0]; v.y = acc[i][jv*4+1];
            v.z = acc[i][jv*4+2]; v.w = acc[i][jv*4+3];
            if (bias) {
                float4 bv = *(const float4*)&bias[n];
                v.x += bv.x; v.y += bv.y; v.z += bv.z; v.w += bv.w;
            }
            *(float4*)&C[(size_t)m*ldc + n] = v;
        }
    }
}

// logits GEMM + fused exp-rowsum epilogue (K=1024, C stride LDO)
__global__ __launch_bounds__(256) void k_logits(
    const float* __restrict__ A, const float* __restrict__ Bm,
    const float* __restrict__ bias, float* __restrict__ C)
{
    __shared__ float As[16][128];
    __shared__ float Bs[16][128];
    __shared__ float rsum[128];
    const int Kdim = 1024;
    int m0 = blockIdx.y * 128, n0 = blockIdx.x * 128;
    int tid = threadIdx.x;
    int tx = tid & 15, ty = tid >> 4;
    int lr = tid >> 2, lc = tid & 3;
    float acc[8][8];
    #pragma unroll
    for (int i = 0; i < 8; i++)
        #pragma unroll
        for (int j = 0; j < 8; j++) acc[i][j] = 0.f;

    for (int k0 = 0; k0 < Kdim; k0 += 16) {
        #pragma unroll
        for (int i = 0; i < 2; i++) {
            float4 a4 = *(const float4*)&A[(size_t)(m0 + lr + 64*i)*Kdim + k0 + lc*4];
            As[lc*4+0][lr+64*i] = a4.x; As[lc*4+1][lr+64*i] = a4.y;
            As[lc*4+2][lr+64*i] = a4.z; As[lc*4+3][lr+64*i] = a4.w;
            float4 b4 = *(const float4*)&Bm[(size_t)(n0 + lr + 64*i)*Kdim + k0 + lc*4];
            Bs[lc*4+0][lr+64*i] = b4.x; Bs[lc*4+1][lr+64*i] = b4.y;
            Bs[lc*4+2][lr+64*i] = b4.z; Bs[lc*4+3][lr+64*i] = b4.w;
        }
        __syncthreads();
        #pragma unroll
        for (int kk = 0; kk < 16; kk++) {
            float a[8], b[8];
            *(float4*)&a[0] = *(const float4*)&As[kk][ty*8];
            *(float4*)&a[4] = *(const float4*)&As[kk][ty*8+4];
            *(float4*)&b[0] = *(const float4*)&Bs[kk][tx*8];
            *(float4*)&b[4] = *(const float4*)&Bs[kk][tx*8+4];
            #pragma unroll
            for (int i = 0; i < 8; i++)
                #pragma unroll
                for (int j = 0; j < 8; j++)
                    acc[i][j] = fmaf(a[i], b[j], acc[i][j]);
        }
        __syncthreads();
    }
    if (tid < 128) rsum[tid] = 0.f;
    __syncthreads();
    #pragma unroll
    for (int i = 0; i < 8; i++) {
        int m = m0 + ty*8 + i;
        float rp = 0.f;
        #pragma unroll
        for (int jv = 0; jv < 2; jv++) {
            int n = n0 + tx*8 + jv*4;
            float4 bv = *(const float4*)&bias[n];
            float4 v;
            v.x = acc[i][jv*4+0] + bv.x; v.y = acc[i][jv*4+1] + bv.y;
            v.z = acc[i][jv*4+2] + bv.z; v.w = acc[i][jv*4+3] + bv.w;
            rp += fexp(v.x) + fexp(v.y) + fexp(v.z) + fexp(v.w);
            *(float4*)&C[(size_t)m*LDO + n] = v;
        }
        atomicAdd(&rsum[ty*8 + i], rp);
    }
    __syncthreads();
    if (tid < 128) atomicAdd(&g_rowsum[m0 + tid], rsum[tid]);
}

// LSTM gates + cell update. 128 blocks (4 h each), 256 threads.
__global__ __launch_bounds__(256) void k_stepA(
    const float* __restrict__ W_ih, const float* __restrict__ W_hh,
    const float* __restrict__ b_ih, const float* __restrict__ b_hh,
    const float* __restrict__ emb, const int* __restrict__ outp, int t)
{
    extern __shared__ float sx[];                 // [8][1536] + gsh[128]
    float* gsh = sx + 8*1536;                     // [16][8]
    int tid = threadIdx.x;
    for (int i = tid; i < BB*HH; i += 256) {
        int b = i >> 9, j = i & 511;
        sx[b*1536 + j]        = g_a[i];
        sx[b*1536 + 1024 + j] = g_hx[i];
        sx[b*1536 + 512  + j] = emb[(size_t)outp[b*TT + t]*HH + j];
    }
    __syncthreads();

    int warp = tid >> 5, lane = tid & 31;
    int hbase = blockIdx.x << 2;
    int rl0 = warp*2, rl1 = rl0 + 1;
    int r0 = (rl0 >> 2)*512 + hbase + (rl0 & 3);
    int r1 = (rl1 >> 2)*512 + hbase + (rl1 & 3);

    float acc0[8], acc1[8];
    #pragma unroll
    for (int b = 0; b < 8; b++) { acc0[b] = 0.f; acc1[b] = 0.f; }

    const float4* wa0 = (const float4*)(W_ih + (size_t)r0*1024);
    const float4* wa1 = (const float4*)(W_ih + (size_t)r1*1024);
    #pragma unroll
    for (int i = 0; i < 8; i++) {
        float4 w0 = wa0[i*32 + lane];
        float4 w1 = wa1[i*32 + lane];
        #pragma unroll
        for (int b = 0; b < 8; b++) {
            float4 x = *(const float4*)&sx[b*1536 + ((i*32 + lane) << 2)];
            acc0[b] = fmaf(w0.x,x.x, fmaf(w0.y,x.y, fmaf(w0.z,x.z, fmaf(w0.w,x.w, acc0[b]))));
            acc1[b] = fmaf(w1.x,x.x, fmaf(w1.y,x.y, fmaf(w1.z,x.z, fmaf(w1.w,x.w, acc1[b]))));
        }
    }
    const float4* wb0 = (const float4*)(W_hh + (size_t)r0*512);
    const float4* wb1 = (const float4*)(W_hh + (size_t)r1*512);
    #pragma unroll
    for (int i = 0; i < 4; i++) {
        float4 w0 = wb0[i*32 + lane];
        float4 w1 = wb1[i*32 + lane];
        #pragma unroll
        for (int b = 0; b < 8; b++) {
            float4 x = *(const float4*)&sx[b*1536 + 1024 + ((i*32 + lane) << 2)];
            acc0[b] = fmaf(w0.x,x.x, fmaf(w0.y,x.y, fmaf(w0.z,x.z, fmaf(w0.w,x.w, acc0[b]))));
            acc1[b] = fmaf(w1.x,x.x, fmaf(w1.y,x.y, fmaf(w1.z,x.z, fmaf(w1.w,x.w, acc1[b]))));
        }
    }
    #pragma unroll
    for (int b = 0; b < 8; b++) {
        float v0 = acc0[b], v1 = acc1[b];
        #pragma unroll
        for (int o = 16; o; o >>= 1) {
            v0 += __shfl_xor_sync(0xffffffffu, v0, o);
            v1 += __shfl_xor_sync(0xffffffffu, v1, o);
        }
        if (lane == 0) {
            gsh[rl0*8 + b] = v0 + b_ih[r0] + b_hh[r0];
            gsh[rl1*8 + b] = v1 + b_ih[r1] + b_hh[r1];
        }
    }
    __syncthreads();
    if (tid < 32) {
        int hh2 = tid >> 3, b = tid & 7;
        int h = hbase + hh2;
        float gi = gsh[(     hh2)*8 + b];
        float gf = gsh[( 4 + hh2)*8 + b];
        float gg = gsh[( 8 + hh2)*8 + b];
        float go = gsh[(12 + hh2)*8 + b];
        float c  = sigf(gf)*g_cx[b*HH + h] + sigf(gi)*tanhf(gg);
        float hx = sigf(go)*tanhf(c);
        g_cx[b*HH + h] = c;
        g_hx[b*HH + h] = hx;
        g_l[((size_t)(b*TT + t))*1024 + h] = hx;
    }
}

// MHA: 32 blocks = (b, head), 128 threads
__global__ __launch_bounds__(128) void k_stepB(
    const float* __restrict__ Wq, const int* __restrict__ entlens, int t)
{
    __shared__ float hxs[HH];
    __shared__ float qs[HD];
    __shared__ float sc[NEN];
    __shared__ float red[4];
    int b = blockIdx.x >> 2, hd = blockIdx.x & 3;
    int tid = threadIdx.x;

    for (int i = tid; i < HH; i += 128) hxs[i] = g_hx[b*HH + i];
    __syncthreads();
    {
        float acc = 0.f;
        const float4* w4 = (const float4*)(Wq + (size_t)(hd*HD + tid)*HH);
        const float4* x4 = (const float4*)hxs;
        #pragma unroll 8
        for (int i = 0; i < HH/4; i++) {
            float4 w = w4[i], x = x4[i];
            acc = fmaf(w.x,x.x, fmaf(w.y,x.y, fmaf(w.z,x.z, fmaf(w.w,x.w, acc))));
        }
        qs[tid] = acc;
    }
    __syncthreads();
    int len = entlens[b];
    if (tid < NEN) {
        float sv = -1e30f;
        if (tid <= len) {
            float acc = 0.f;
            const float4* k4 = (const float4*)(g_K + (size_t)(b*NEN + tid)*HH + hd*HD);
            const float4* q4 = (const float4*)qs;
            #pragma unroll 8
            for (int i = 0; i < HD/4; i++) {
                float4 kv = k4[i], qv = q4[i];
                acc = fmaf(kv.x,qv.x, fmaf(kv.y,qv.y, fmaf(kv.z,qv.z, fmaf(kv.w,qv.w, acc))));
            }
            sv = acc * 0.04419417382415922f;   // 1/sqrt(512)
        }
        sc[tid] = sv;
    }
    __syncthreads();
    float v = (tid < NEN) ? sc[tid] : -1e30f;
    #pragma unroll
    for (int o = 16; o; o >>= 1) v = fmaxf(v, __shfl_xor_sync(0xffffffffu, v, o));
    if ((tid & 31) == 0) red[tid >> 5] = v;
    __syncthreads();
    float m = fmaxf(fmaxf(red[0], red[1]), fmaxf(red[2], red[3]));
    __syncthreads();
    float e = 0.f;
    if (tid < NEN && tid <= len) e = __expf(sc[tid] - m);
    float s2 = e;
    #pragma unroll
    for (int o = 16; o; o >>= 1) s2 += __shfl_xor_sync(0xffffffffu, s2, o);
    if ((tid & 31) == 0) red[tid >> 5] = s2;
    __syncthreads();
    float inv = 1.0f / (red[0] + red[1] + red[2] + red[3]);
    __syncthreads();
    if (tid < NEN) sc[tid] = e * inv;
    __syncthreads();
    {
        float acc = 0.f;
        const float* vb = g_V + (size_t)b*NEN*HH + hd*HD + tid;
        #pragma unroll 8
        for (int n = 0; n < NEN; n++) acc = fmaf(sc[n], vb[(size_t)n*HH], acc);
        g_a[b*HH + hd*HD + tid] = acc;
        g_l[((size_t)(b*TT + t))*1024 + 512 + hd*HD + tid] = acc;
    }
}

__global__ __launch_bounds__(256) void k_switch(
    const float* __restrict__ sw_W, const float* __restrict__ sw_b)
{
    int r = blockIdx.x*8 + (threadIdx.x >> 5);
    int lane = threadIdx.x & 31;
    const float4* l4 = (const float4*)(g_l + (size_t)r*1024);
    const float4* w4 = (const float4*)sw_W;
    float acc = 0.f;
    #pragma unroll
    for (int i = 0; i < 8; i++) {
        float4 a = l4[i*32 + lane], w = w4[i*32 + lane];
        acc = fmaf(a.x,w.x, fmaf(a.y,w.y, fmaf(a.z,w.z, fmaf(a.w,w.w, acc))));
    }
    #pragma unroll
    for (int o = 16; o; o >>= 1) acc += __shfl_xor_sync(0xffffffffu, acc, o);
    if (lane == 0) g_s[r] = sigf(acc + sw_b[0]);
}

__global__ __launch_bounds__(64) void k_ptr(
    const float* __restrict__ ents, const int* __restrict__ entlens,
    float* __restrict__ out, int write_tail)
{
    __shared__ float ds[HH];
    __shared__ float red[2];
    int r = blockIdx.x;
    int b = r >> 8;
    int tid = threadIdx.x;
    for (int i = tid; i < HH; i += 64) ds[i] = g_dec[(size_t)r*HH + i];
    __syncthreads();
    int len = entlens[b];
    float sv = -1e30f;
    if (tid <= len) {
        float acc = 0.f;
        const float4* e4 = (const float4*)(ents + (size_t)(b*NEN + tid)*HH);
        const float4* d4 = (const float4*)ds;
        #pragma unroll 8
        for (int i = 0; i < HH/4; i++) {
            float4 ev = e4[i], dv = d4[i];
            acc = fmaf(ev.x,dv.x, fmaf(ev.y,dv.y, fmaf(ev.z,dv.z, fmaf(ev.w,dv.w, acc))));
        }
        sv = acc;
    }
    float v = sv;
    #pragma unroll
    for (int o = 16; o; o >>= 1) v = fmaxf(v, __shfl_xor_sync(0xffffffffu, v, o));
    if ((tid & 31) == 0) red[tid >> 5] = v;
    __syncthreads();
    float m = fmaxf(red[0], red[1]);
    float e = (tid <= len) ? __expf(sv - m) : 0.f;
    float s2 = e;
    #pragma unroll
    for (int o = 16; o; o >>= 1) s2 += __shfl_xor_sync(0xffffffffu, s2, o);
    if ((tid & 31) == 0) red[tid >> 5] = s2;
    __syncthreads();
    float inv = 1.0f / (red[0] + red[1]);
    float s = g_s[r];
    float z = e * inv * (1.0f - s);
    out[(size_t)r*LDO + VOCAB + tid] = __logf(z + 1e-6f);
    if (write_tail) out[(size_t)NROWS*LDO + (size_t)r*NEN + tid] = z;
}

__global__ void k_rowc() {
    int r = blockIdx.x*256 + threadIdx.x;
    if (r < NROWS) g_c[r] = g_s[r] / g_rowsum[r];
}

__global__ __launch_bounds__(256) void k_final(float* __restrict__ out) {
    int r = blockIdx.x;
    float c = g_c[r];
    float4* row = (float4*)(out + (size_t)r*LDO);
    for (int i = threadIdx.x; i < VOCAB/4; i += 256) {
        float4 v = row[i];
        v.x = __logf(fmaf(fexp(v.x), c, 1e-6f));
        v.y = __logf(fmaf(fexp(v.y), c, 1e-6f));
        v.z = __logf(fmaf(fexp(v.z), c, 1e-6f));
        v.w = __logf(fmaf(fexp(v.w), c, 1e-6f));
        row[i] = v;
    }
}

extern "C" void kernel_launch(void* const* d_in, const int* in_sizes, int n_in,
                              void* d_out, int out_size)
{
    const int*   outp    = (const int*)  d_in[0];
    const float* ents    = (const float*)d_in[1];
    const int*   entlens = (const int*)  d_in[2];
    const float* emb     = (const float*)d_in[3];
    const float* W_ih    = (const float*)d_in[4];
    const float* W_hh    = (const float*)d_in[5];
    const float* b_ih    = (const float*)d_in[6];
    const float* b_hh    = (const float*)d_in[7];
    const float* Wq      = (const float*)d_in[8];
    const float* Wk      = (const float*)d_in[9];
    const float* Wv      = (const float*)d_in[10];
    const float* out_W   = (const float*)d_in[11];
    const float* out_b   = (const float*)d_in[12];
    const float* sw_W    = (const float*)d_in[13];
    const float* sw_b    = (const float*)d_in[14];
    const float* mattn_W = (const float*)d_in[15];
    const float* mattn_b = (const float*)d_in[16];
    float* out = (float*)d_out;

    static int smem_set = 0;
    if (!smem_set) {
        cudaFuncSetAttribute(k_stepA, cudaFuncAttributeMaxDynamicSharedMemorySize, 64*1024);
        smem_set = 1;
    }
    const int stepA_smem = (8*1536 + 128) * 4;

    float *g_K_p, *g_V_p, *g_l_p, *g_dec_p;
    cudaGetSymbolAddress((void**)&g_K_p, g_K);
    cudaGetSymbolAddress((void**)&g_V_p, g_V);
    cudaGetSymbolAddress((void**)&g_l_p, g_l);
    cudaGetSymbolAddress((void**)&g_dec_p, g_dec);

    k_init<<<12, 512>>>(ents);
    k_sgemm<<<dim3(4,4), 256>>>(ents, Wk, nullptr, g_K_p, 512, 512);
    k_sgemm<<<dim3(4,4), 256>>>(ents, Wv, nullptr, g_V_p, 512, 512);

    for (int t = 0; t < TT; t++) {
        k_stepA<<<128, 256, stepA_smem>>>(W_ih, W_hh, b_ih, b_hh, emb, outp, t);
        k_stepB<<<32, 128>>>(Wq, entlens, t);
    }

    k_switch<<<NROWS/8, 256>>>(sw_W, sw_b);
    k_sgemm<<<dim3(4,16), 256>>>(g_l_p, mattn_W, mattn_b, g_dec_p, 1024, 512);
    k_logits<<<dim3(VOCAB/128, NROWS/128), 256>>>(g_l_p, out_W, out_b, out);
    k_rowc<<<8, 256>>>();
    int write_tail = (out_size >= NROWS*LDO + NROWS*NEN) ? 1 : 0;
    k_ptr<<<NROWS, 64>>>(ents, entlens, out, write_tail);
    k_final<<<NROWS, 256>>>(out);
}

// round 4
// speedup vs baseline: 1.2734x; 1.2734x over previous
#include <cuda_runtime.h>
#include <cuda_bf16.h>
#include <cstdint>
#include <cstddef>

#define BB     8
#define TT     256
#define NEN    64
#define HH     512
#define HD     128
#define VOCAB  32000
#define NROWS  (BB*TT)
#define LDO    (VOCAB+NEN)

__device__ float g_K[BB*NEN*HH];
__device__ float g_V[BB*NEN*HH];
__device__ float g_hx[BB*HH];
__device__ float g_cx[BB*HH];
__device__ float g_a[BB*HH];
__device__ float g_l[(size_t)NROWS*2*HH];
__device__ float g_dec[(size_t)NROWS*HH];
__device__ float g_s[NROWS];
__device__ float g_rowsum[NROWS];
__device__ float g_c[NROWS];
__device__ __nv_bfloat16 g_Wb[(size_t)VOCAB*1024];
__device__ __nv_bfloat16 g_lb[(size_t)NROWS*1024];

__device__ __forceinline__ float sigf(float x) { return 1.0f / (1.0f + __expf(-x)); }

__device__ __forceinline__ float fexp(float x) {
    float z = x * 1.44269504088896f;
    float r = z + 12582912.0f;
    int   n = __float_as_int(r) - 0x4B400000;
    float f = z - (r - 12582912.0f);
    float p = 1.33336498e-3f;
    p = fmaf(p, f, 9.61011474e-3f);
    p = fmaf(p, f, 5.55036190e-2f);
    p = fmaf(p, f, 2.40226337e-1f);
    p = fmaf(p, f, 6.93147182e-1f);
    p = fmaf(p, f, 1.0f);
    return p * __int_as_float((n + 127) << 23);
}

__global__ void k_init(const float* __restrict__ ents) {
    int blk = blockIdx.x;
    if (blk < BB) {
        int b = blk, h = threadIdx.x;
        float s = 0.f;
        #pragma unroll 8
        for (int n = 0; n < NEN; n++) s += ents[(size_t)(b*NEN + n)*HH + h];
        s *= (1.0f / NEN);
        g_hx[b*HH + h] = s;
        g_cx[b*HH + h] = s;
        g_a [b*HH + h] = 0.f;
    } else {
        int i = (blk - BB)*512 + threadIdx.x;
        if (i < NROWS) g_rowsum[i] = 0.f;
    }
}

// fp32 -> bf16 weight conversion (out_W)
__global__ __launch_bounds__(256) void k_cvtw(const float* __restrict__ W) {
    size_t i = ((size_t)blockIdx.x*256 + threadIdx.x)*4;
    float4 v = *(const float4*)&W[i];
    __nv_bfloat162 p0 = __nv_bfloat162(__float2bfloat16(v.x), __float2bfloat16(v.y));
    __nv_bfloat162 p1 = __nv_bfloat162(__float2bfloat16(v.z), __float2bfloat16(v.w));
    *(__nv_bfloat162*)&g_Wb[i]   = p0;
    *(__nv_bfloat162*)&g_Wb[i+2] = p1;
}

// generic fp32 SGEMM: C[M,N] = A[M,K]@Bm[N,K]^T + bias (used for K/V/dec)
__global__ __launch_bounds__(256) void k_sgemm(
    const float* __restrict__ A, const float* __restrict__ Bm,
    const float* __restrict__ bias, float* __restrict__ C, int Kdim, int ldc)
{
    __shared__ float As[16][128];
    __shared__ float Bs[16][128];
    int m0 = blockIdx.y * 128, n0 = blockIdx.x * 128;
    int tid = threadIdx.x;
    int tx = tid & 15, ty = tid >> 4;
    int lr = tid >> 2, lc = tid & 3;
    float acc[8][8];
    #pragma unroll
    for (int i = 0; i < 8; i++)
        #pragma unroll
        for (int j = 0; j < 8; j++) acc[i][j] = 0.f;

    for (int k0 = 0; k0 < Kdim; k0 += 16) {
        #pragma unroll
        for (int i = 0; i < 2; i++) {
            float4 a4 = *(const float4*)&A[(size_t)(m0 + lr + 64*i)*Kdim + k0 + lc*4];
            As[lc*4+0][lr+64*i] = a4.x; As[lc*4+1][lr+64*i] = a4.y;
            As[lc*4+2][lr+64*i] = a4.z; As[lc*4+3][lr+64*i] = a4.w;
            float4 b4 = *(const float4*)&Bm[(size_t)(n0 + lr + 64*i)*Kdim + k0 + lc*4];
            Bs[lc*4+0][lr+64*i] = b4.x; Bs[lc*4+1][lr+64*i] = b4.y;
            Bs[lc*4+2][lr+64*i] = b4.z; Bs[lc*4+3][lr+64*i] = b4.w;
        }
        __syncthreads();
        #pragma unroll
        for (int kk = 0; kk < 16; kk++) {
            float a[8], b[8];
            *(float4*)&a[0] = *(const float4*)&As[kk][ty*8];
            *(float4*)&a[4] = *(const float4*)&As[kk][ty*8+4];
            *(float4*)&b[0] = *(const float4*)&Bs[kk][tx*8];
            *(float4*)&b[4] = *(const float4*)&Bs[kk][tx*8+4];
            #pragma unroll
            for (int i = 0; i < 8; i++)
                #pragma unroll
                for (int j = 0; j < 8; j++)
                    acc[i][j] = fmaf(a[i], b[j], acc[i][j]);
        }
        __syncthreads();
    }
    #pragma unroll
    for (int i = 0; i < 8; i++) {
        int m = m0 + ty*8 + i;
        #pragma unroll
        for (int jv = 0; jv < 2; jv++) {
            int n = n0 + tx*8 + jv*4;
            float4 v;
            v.x = acc[i][jv*4+0]; v.y = acc[i][jv*4+1];
            v.z = acc[i][jv*4+2]; v.w = acc[i][jv*4+3];
            if (bias) {
                float4 bv = *(const float4*)&bias[n];
                v.x += bv.x; v.y += bv.y; v.z += bv.z; v.w += bv.w;
            }
            *(float4*)&C[(size_t)m*ldc + n] = v;
        }
    }
}

// ---------------- bf16 tensor-core logits GEMM + fused exp-rowsum ------------
// C[2048,32000](stride LDO) = A[2048,1024]bf16 @ B[32000,1024]bf16^T + bias
// 128x128x32 tiles, 8 warps (2x4), warp tile 64x32, mma.m16n8k16.
#define PADK 40

__device__ __forceinline__ void ldsm4(uint32_t& r0, uint32_t& r1, uint32_t& r2, uint32_t& r3, uint32_t addr) {
    asm volatile("ldmatrix.sync.aligned.m8n8.x4.shared.b16 {%0,%1,%2,%3}, [%4];"
                 : "=r"(r0), "=r"(r1), "=r"(r2), "=r"(r3) : "r"(addr));
}
__device__ __forceinline__ void mma16816(float* c, const uint32_t* a, const uint32_t* b) {
    asm volatile("mma.sync.aligned.m16n8k16.row.col.f32.bf16.bf16.f32 "
                 "{%0,%1,%2,%3}, {%4,%5,%6,%7}, {%8,%9}, {%0,%1,%2,%3};"
                 : "+f"(c[0]), "+f"(c[1]), "+f"(c[2]), "+f"(c[3])
                 : "r"(a[0]), "r"(a[1]), "r"(a[2]), "r"(a[3]), "r"(b[0]), "r"(b[1]));
}

__global__ __launch_bounds__(256) void k_logits_mma(
    const float* __restrict__ bias, float* __restrict__ C)
{
    __shared__ __nv_bfloat16 As[2][128*PADK];
    __shared__ __nv_bfloat16 Bs[2][128*PADK];
    __shared__ float rsum[128];
    const int Kd = 1024;
    const __nv_bfloat16* A = g_lb;
    const __nv_bfloat16* B = g_Wb;
    int m0 = blockIdx.y*128, n0 = blockIdx.x*128;
    int tid = threadIdx.x;
    int warp = tid >> 5, lane = tid & 31;
    int wm = warp >> 2, wn = warp & 3;

    // staging: thread -> (row, 32B half)
    int srow = tid & 127;
    int shalf = tid >> 7;            // 0/1, each 16 bf16
    const __nv_bfloat16* gA = A + (size_t)(m0 + srow)*Kd + shalf*16;
    const __nv_bfloat16* gB = B + (size_t)(n0 + srow)*Kd + shalf*16;
    uint32_t sA0 = (uint32_t)__cvta_generic_to_shared(&As[0][srow*PADK + shalf*16]);
    uint32_t sB0 = (uint32_t)__cvta_generic_to_shared(&Bs[0][srow*PADK + shalf*16]);
    const uint32_t bufstrideA = (uint32_t)((char*)&As[1][0] - (char*)&As[0][0]);
    const uint32_t bufstrideB = (uint32_t)((char*)&Bs[1][0] - (char*)&Bs[0][0]);

    float acc[4][4][4];
    #pragma unroll
    for (int i = 0; i < 4; i++)
        #pragma unroll
        for (int j = 0; j < 4; j++)
            #pragma unroll
            for (int k = 0; k < 4; k++) acc[i][j][k] = 0.f;

    // ldmatrix addresses (per-thread, fixed row/col pattern within tile)
    int aq = lane >> 3;              // matrix id 0..3
    int arow_off = ((aq & 1) << 3) + (lane & 7);
    int acol_off = (aq >> 1) << 3;
    int brow_off = ((aq >> 1) << 3) + (lane & 7);
    int bcol_off = (aq & 1) << 3;

    // prefetch stage 0
    #pragma unroll
    for (int s = 0; s < 2; s++) {
        asm volatile("cp.async.cg.shared.global [%0], [%1], 16;" ::
                     "r"(sA0 + s*16), "l"(gA + s*8));
        asm volatile("cp.async.cg.shared.global [%0], [%1], 16;" ::
                     "r"(sB0 + s*16), "l"(gB + s*8));
    }
    asm volatile("cp.async.commit_group;");

    const int NIT = Kd/32;
    for (int it = 0; it < NIT; it++) {
        int buf = it & 1;
        if (it + 1 < NIT) {
            uint32_t sa = sA0 + ((it+1)&1)*bufstrideA;
            uint32_t sb = sB0 + ((it+1)&1)*bufstrideB;
            const __nv_bfloat16* ga = gA + (it+1)*32;
            const __nv_bfloat16* gb = gB + (it+1)*32;
            #pragma unroll
            for (int s = 0; s < 2; s++) {
                asm volatile("cp.async.cg.shared.global [%0], [%1], 16;" ::
                             "r"(sa + s*16), "l"(ga + s*8));
                asm volatile("cp.async.cg.shared.global [%0], [%1], 16;" ::
                             "r"(sb + s*16), "l"(gb + s*8));
            }
            asm volatile("cp.async.commit_group;");
            asm volatile("cp.async.wait_group 1;");
        } else {
            asm volatile("cp.async.wait_group 0;");
        }
        __syncthreads();

        #pragma unroll
        for (int kk = 0; kk < 2; kk++) {
            uint32_t aF[4][4], bF[4][2];
            #pragma unroll
            for (int mi = 0; mi < 4; mi++) {
                int row = wm*64 + mi*16 + arow_off;
                int col = kk*16 + acol_off;
                uint32_t ad = (uint32_t)__cvta_generic_to_shared(&As[buf][row*PADK + col]);
                ldsm4(aF[mi][0], aF[mi][1], aF[mi][2], aF[mi][3], ad);
            }
            #pragma unroll
            for (int np = 0; np < 2; np++) {
                int row = wn*32 + np*16 + brow_off;
                int col = kk*16 + bcol_off;
                uint32_t bd = (uint32_t)__cvta_generic_to_shared(&Bs[buf][row*PADK + col]);
                ldsm4(bF[np*2][0], bF[np*2][1], bF[np*2+1][0], bF[np*2+1][1], bd);
            }
            #pragma unroll
            for (int mi = 0; mi < 4; mi++)
                #pragma unroll
                for (int ni = 0; ni < 4; ni++)
                    mma16816(acc[mi][ni], aF[mi], bF[ni]);
        }
        __syncthreads();
    }

    if (tid < 128) rsum[tid] = 0.f;
    __syncthreads();

    int g = lane >> 2, tg = lane & 3;
    #pragma unroll
    for (int mi = 0; mi < 4; mi++) {
        int r0l = wm*64 + mi*16 + g;
        int r1l = r0l + 8;
        float rp0 = 0.f, rp1 = 0.f;
        #pragma unroll
        for (int ni = 0; ni < 4; ni++) {
            int n = n0 + wn*32 + ni*8 + tg*2;
            float2 bv = *(const float2*)&bias[n];
            float v0 = acc[mi][ni][0] + bv.x;
            float v1 = acc[mi][ni][1] + bv.y;
            float v2 = acc[mi][ni][2] + bv.x;
            float v3 = acc[mi][ni][3] + bv.y;
            float2 w0; w0.x = v0; w0.y = v1;
            float2 w1; w1.x = v2; w1.y = v3;
            *(float2*)&C[(size_t)(m0 + r0l)*LDO + n] = w0;
            *(float2*)&C[(size_t)(m0 + r1l)*LDO + n] = w1;
            rp0 += fexp(v0) + fexp(v1);
            rp1 += fexp(v2) + fexp(v3);
        }
        atomicAdd(&rsum[r0l], rp0);
        atomicAdd(&rsum[r1l], rp1);
    }
    __syncthreads();
    if (tid < 128) atomicAdd(&g_rowsum[m0 + tid], rsum[tid]);
}

// LSTM gates + cell update. 128 blocks (4 h each), 256 threads.
__global__ __launch_bounds__(256) void k_stepA(
    const float* __restrict__ W_ih, const float* __restrict__ W_hh,
    const float* __restrict__ b_ih, const float* __restrict__ b_hh,
    const float* __restrict__ emb, const int* __restrict__ outp, int t)
{
    extern __shared__ float sx[];
    float* gsh = sx + 8*1536;
    int tid = threadIdx.x;
    for (int i = tid; i < BB*HH; i += 256) {
        int b = i >> 9, j = i & 511;
        sx[b*1536 + j]        = g_a[i];
        sx[b*1536 + 1024 + j] = g_hx[i];
        sx[b*1536 + 512  + j] = emb[(size_t)outp[b*TT + t]*HH + j];
    }
    __syncthreads();

    int warp = tid >> 5, lane = tid & 31;
    int hbase = blockIdx.x << 2;
    int rl0 = warp*2, rl1 = rl0 + 1;
    int r0 = (rl0 >> 2)*512 + hbase + (rl0 & 3);
    int r1 = (rl1 >> 2)*512 + hbase + (rl1 & 3);

    float acc0[8], acc1[8];
    #pragma unroll
    for (int b = 0; b < 8; b++) { acc0[b] = 0.f; acc1[b] = 0.f; }

    const float4* wa0 = (const float4*)(W_ih + (size_t)r0*1024);
    const float4* wa1 = (const float4*)(W_ih + (size_t)r1*1024);
    #pragma unroll
    for (int i = 0; i < 8; i++) {
        float4 w0 = wa0[i*32 + lane];
        float4 w1 = wa1[i*32 + lane];
        #pragma unroll
        for (int b = 0; b < 8; b++) {
            float4 x = *(const float4*)&sx[b*1536 + ((i*32 + lane) << 2)];
            acc0[b] = fmaf(w0.x,x.x, fmaf(w0.y,x.y, fmaf(w0.z,x.z, fmaf(w0.w,x.w, acc0[b]))));
            acc1[b] = fmaf(w1.x,x.x, fmaf(w1.y,x.y, fmaf(w1.z,x.z, fmaf(w1.w,x.w, acc1[b]))));
        }
    }
    const float4* wb0 = (const float4*)(W_hh + (size_t)r0*512);
    const float4* wb1 = (const float4*)(W_hh + (size_t)r1*512);
    #pragma unroll
    for (int i = 0; i < 4; i++) {
        float4 w0 = wb0[i*32 + lane];
        float4 w1 = wb1[i*32 + lane];
        #pragma unroll
        for (int b = 0; b < 8; b++) {
            float4 x = *(const float4*)&sx[b*1536 + 1024 + ((i*32 + lane) << 2)];
            acc0[b] = fmaf(w0.x,x.x, fmaf(w0.y,x.y, fmaf(w0.z,x.z, fmaf(w0.w,x.w, acc0[b]))));
            acc1[b] = fmaf(w1.x,x.x, fmaf(w1.y,x.y, fmaf(w1.z,x.z, fmaf(w1.w,x.w, acc1[b]))));
        }
    }
    #pragma unroll
    for (int b = 0; b < 8; b++) {
        float v0 = acc0[b], v1 = acc1[b];
        #pragma unroll
        for (int o = 16; o; o >>= 1) {
            v0 += __shfl_xor_sync(0xffffffffu, v0, o);
            v1 += __shfl_xor_sync(0xffffffffu, v1, o);
        }
        if (lane == 0) {
            gsh[rl0*8 + b] = v0 + b_ih[r0] + b_hh[r0];
            gsh[rl1*8 + b] = v1 + b_ih[r1] + b_hh[r1];
        }
    }
    __syncthreads();
    if (tid < 32) {
        int hh2 = tid >> 3, b = tid & 7;
        int h = hbase + hh2;
        float gi = gsh[(     hh2)*8 + b];
        float gf = gsh[( 4 + hh2)*8 + b];
        float gg = gsh[( 8 + hh2)*8 + b];
        float go = gsh[(12 + hh2)*8 + b];
        float c  = sigf(gf)*g_cx[b*HH + h] + sigf(gi)*tanhf(gg);
        float hx = sigf(go)*tanhf(c);
        g_cx[b*HH + h] = c;
        g_hx[b*HH + h] = hx;
        size_t li = ((size_t)(b*TT + t))*1024 + h;
        g_l[li]  = hx;
        g_lb[li] = __float2bfloat16(hx);
    }
}

// MHA: 32 blocks = (b, head), 128 threads
__global__ __launch_bounds__(128) void k_stepB(
    const float* __restrict__ Wq, const int* __restrict__ entlens, int t)
{
    __shared__ float hxs[HH];
    __shared__ float qs[HD];
    __shared__ float sc[NEN];
    __shared__ float red[4];
    int b = blockIdx.x >> 2, hd = blockIdx.x & 3;
    int tid = threadIdx.x;

    for (int i = tid; i < HH; i += 128) hxs[i] = g_hx[b*HH + i];
    __syncthreads();
    {
        float acc = 0.f;
        const float4* w4 = (const float4*)(Wq + (size_t)(hd*HD + tid)*HH);
        const float4* x4 = (const float4*)hxs;
        #pragma unroll 8
        for (int i = 0; i < HH/4; i++) {
            float4 w = w4[i], x = x4[i];
            acc = fmaf(w.x,x.x, fmaf(w.y,x.y, fmaf(w.z,x.z, fmaf(w.w,x.w, acc))));
        }
        qs[tid] = acc;
    }
    __syncthreads();
    int len = entlens[b];
    if (tid < NEN) {
        float sv = -1e30f;
        if (tid <= len) {
            float acc = 0.f;
            const float4* k4 = (const float4*)(g_K + (size_t)(b*NEN + tid)*HH + hd*HD);
            const float4* q4 = (const float4*)qs;
            #pragma unroll 8
            for (int i = 0; i < HD/4; i++) {
                float4 kv = k4[i], qv = q4[i];
                acc = fmaf(kv.x,qv.x, fmaf(kv.y,qv.y, fmaf(kv.z,qv.z, fmaf(kv.w,qv.w, acc))));
            }
            sv = acc * 0.04419417382415922f;
        }
        sc[tid] = sv;
    }
    __syncthreads();
    float v = (tid < NEN) ? sc[tid] : -1e30f;
    #pragma unroll
    for (int o = 16; o; o >>= 1) v = fmaxf(v, __shfl_xor_sync(0xffffffffu, v, o));
    if ((tid & 31) == 0) red[tid >> 5] = v;
    __syncthreads();
    float m = fmaxf(fmaxf(red[0], red[1]), fmaxf(red[2], red[3]));
    __syncthreads();
    float e = 0.f;
    if (tid < NEN && tid <= len) e = __expf(sc[tid] - m);
    float s2 = e;
    #pragma unroll
    for (int o = 16; o; o >>= 1) s2 += __shfl_xor_sync(0xffffffffu, s2, o);
    if ((tid & 31) == 0) red[tid >> 5] = s2;
    __syncthreads();
    float inv = 1.0f / (red[0] + red[1] + red[2] + red[3]);
    __syncthreads();
    if (tid < NEN) sc[tid] = e * inv;
    __syncthreads();
    {
        float acc = 0.f;
        const float* vb = g_V + (size_t)b*NEN*HH + hd*HD + tid;
        #pragma unroll 8
        for (int n = 0; n < NEN; n++) acc = fmaf(sc[n], vb[(size_t)n*HH], acc);
        g_a[b*HH + hd*HD + tid] = acc;
        size_t li = ((size_t)(b*TT + t))*1024 + 512 + hd*HD + tid;
        g_l[li]  = acc;
        g_lb[li] = __float2bfloat16(acc);
    }
}

__global__ __launch_bounds__(256) void k_switch(
    const float* __restrict__ sw_W, const float* __restrict__ sw_b)
{
    int r = blockIdx.x*8 + (threadIdx.x >> 5);
    int lane = threadIdx.x & 31;
    const float4* l4 = (const float4*)(g_l + (size_t)r*1024);
    const float4* w4 = (const float4*)sw_W;
    float acc = 0.f;
    #pragma unroll
    for (int i = 0; i < 8; i++) {
        float4 a = l4[i*32 + lane], w = w4[i*32 + lane];
        acc = fmaf(a.x,w.x, fmaf(a.y,w.y, fmaf(a.z,w.z, fmaf(a.w,w.w, acc))));
    }
    #pragma unroll
    for (int o = 16; o; o >>= 1) acc += __shfl_xor_sync(0xffffffffu, acc, o);
    if (lane == 0) g_s[r] = sigf(acc + sw_b[0]);
}

__global__ __launch_bounds__(64) void k_ptr(
    const float* __restrict__ ents, const int* __restrict__ entlens,
    float* __restrict__ out, int write_tail)
{
    __shared__ float ds[HH];
    __shared__ float red[2];
    int r = blockIdx.x;
    int b = r >> 8;
    int tid = threadIdx.x;
    for (int i = tid; i < HH; i += 64) ds[i] = g_dec[(size_t)r*HH + i];
    __syncthreads();
    int len = entlens[b];
    float sv = -1e30f;
    if (tid <= len) {
        float acc = 0.f;
        const float4* e4 = (const float4*)(ents + (size_t)(b*NEN + tid)*HH);
        const float4* d4 = (const float4*)ds;
        #pragma unroll 8
        for (int i = 0; i < HH/4; i++) {
            float4 ev = e4[i], dv = d4[i];
            acc = fmaf(ev.x,dv.x, fmaf(ev.y,dv.y, fmaf(ev.z,dv.z, fmaf(ev.w,dv.w, acc))));
        }
        sv = acc;
    }
    float v = sv;
    #pragma unroll
    for (int o = 16; o; o >>= 1) v = fmaxf(v, __shfl_xor_sync(0xffffffffu, v, o));
    if ((tid & 31) == 0) red[tid >> 5] = v;
    __syncthreads();
    float m = fmaxf(red[0], red[1]);
    float e = (tid <= len) ? __expf(sv - m) : 0.f;
    float s2 = e;
    #pragma unroll
    for (int o = 16; o; o >>= 1) s2 += __shfl_xor_sync(0xffffffffu, s2, o);
    if ((tid & 31) == 0) red[tid >> 5] = s2;
    __syncthreads();
    float inv = 1.0f / (red[0] + red[1]);
    float s = g_s[r];
    float z = e * inv * (1.0f - s);
    out[(size_t)r*LDO + VOCAB + tid] = __logf(z + 1e-6f);
    if (write_tail) out[(size_t)NROWS*LDO + (size_t)r*NEN + tid] = z;
}

__global__ void k_rowc() {
    int r = blockIdx.x*256 + threadIdx.x;
    if (r < NROWS) g_c[r] = g_s[r] / g_rowsum[r];
}

__global__ __launch_bounds__(256) void k_final(float* __restrict__ out) {
    int r = blockIdx.x;
    float c = g_c[r];
    float4* row = (float4*)(out + (size_t)r*LDO);
    for (int i = threadIdx.x; i < VOCAB/4; i += 256) {
        float4 v = row[i];
        v.x = __logf(fmaf(fexp(v.x), c, 1e-6f));
        v.y = __logf(fmaf(fexp(v.y), c, 1e-6f));
        v.z = __logf(fmaf(fexp(v.z), c, 1e-6f));
        v.w = __logf(fmaf(fexp(v.w), c, 1e-6f));
        row[i] = v;
    }
}

extern "C" void kernel_launch(void* const* d_in, const int* in_sizes, int n_in,
                              void* d_out, int out_size)
{
    const int*   outp    = (const int*)  d_in[0];
    const float* ents    = (const float*)d_in[1];
    const int*   entlens = (const int*)  d_in[2];
    const float* emb     = (const float*)d_in[3];
    const float* W_ih    = (const float*)d_in[4];
    const float* W_hh    = (const float*)d_in[5];
    const float* b_ih    = (const float*)d_in[6];
    const float* b_hh    = (const float*)d_in[7];
    const float* Wq      = (const float*)d_in[8];
    const float* Wk      = (const float*)d_in[9];
    const float* Wv      = (const float*)d_in[10];
    const float* out_W   = (const float*)d_in[11];
    const float* out_b   = (const float*)d_in[12];
    const float* sw_W    = (const float*)d_in[13];
    const float* sw_b    = (const float*)d_in[14];
    const float* mattn_W = (const float*)d_in[15];
    const float* mattn_b = (const float*)d_in[16];
    float* out = (float*)d_out;

    static int smem_set = 0;
    if (!smem_set) {
        cudaFuncSetAttribute(k_stepA, cudaFuncAttributeMaxDynamicSharedMemorySize, 64*1024);
        smem_set = 1;
    }
    const int stepA_smem = (8*1536 + 128) * 4;

    float *g_K_p, *g_V_p, *g_l_p, *g_dec_p;
    cudaGetSymbolAddress((void**)&g_K_p, g_K);
    cudaGetSymbolAddress((void**)&g_V_p, g_V);
    cudaGetSymbolAddress((void**)&g_l_p, g_l);
    cudaGetSymbolAddress((void**)&g_dec_p, g_dec);

    k_init<<<12, 512>>>(ents);
    k_cvtw<<<VOCAB*1024/(256*4), 256>>>(out_W);
    k_sgemm<<<dim3(4,4), 256>>>(ents, Wk, nullptr, g_K_p, 512, 512);
    k_sgemm<<<dim3(4,4), 256>>>(ents, Wv, nullptr, g_V_p, 512, 512);

    for (int t = 0; t < TT; t++) {
        k_stepA<<<128, 256, stepA_smem>>>(W_ih, W_hh, b_ih, b_hh, emb, outp, t);
        k_stepB<<<32, 128>>>(Wq, entlens, t);
    }

    k_switch<<<NROWS/8, 256>>>(sw_W, sw_b);
    k_sgemm<<<dim3(4,16), 256>>>(g_l_p, mattn_W, mattn_b, g_dec_p, 1024, 512);
    k_logits_mma<<<dim3(VOCAB/128, NROWS/128), 256>>>(out_b, out);
    k_rowc<<<8, 256>>>();
    int write_tail = (out_size >= NROWS*LDO + NROWS*NEN) ? 1 : 0;
    k_ptr<<<NROWS, 64>>>(ents, entlens, out, write_tail);
    k_final<<<NROWS, 256>>>(out);
}

// round 5
// speedup vs baseline: 1.5905x; 1.2490x over previous
#include <cuda_runtime.h>
#include <cuda_bf16.h>
#include <cstdint>
#include <cstddef>

#define BB     8
#define TT     256
#define NEN    64
#define HH     512
#define HD     128
#define VOCAB  32000
#define NROWS  (BB*TT)
#define LDO    (VOCAB+NEN)
#define GRIDN  128

__device__ float g_K[BB*NEN*HH];
__device__ float g_V[BB*NEN*HH];
__device__ float g_hx[BB*HH];
__device__ float g_cx[BB*HH];
__device__ float g_a[BB*HH];
__device__ float g_l[(size_t)NROWS*2*HH];
__device__ float g_dec[(size_t)NROWS*HH];
__device__ float g_s[NROWS];
__device__ float g_rowsum[NROWS];
__device__ float g_c[NROWS];
__device__ unsigned g_barcnt;
__device__ __nv_bfloat16 g_Wb[(size_t)VOCAB*1024];
__device__ __nv_bfloat16 g_lb[(size_t)NROWS*1024];

__device__ __forceinline__ float sigf(float x) { return 1.0f / (1.0f + __expf(-x)); }

__device__ __forceinline__ float fexp(float x) {
    float z = x * 1.44269504088896f;
    float r = z + 12582912.0f;
    int   n = __float_as_int(r) - 0x4B400000;
    float f = z - (r - 12582912.0f);
    float p = 1.33336498e-3f;
    p = fmaf(p, f, 9.61011474e-3f);
    p = fmaf(p, f, 5.55036190e-2f);
    p = fmaf(p, f, 2.40226337e-1f);
    p = fmaf(p, f, 6.93147182e-1f);
    p = fmaf(p, f, 1.0f);
    return p * __int_as_float((n + 127) << 23);
}

__global__ void k_init(const float* __restrict__ ents) {
    int blk = blockIdx.x;
    if (blk == 0 && threadIdx.x == 0) g_barcnt = 0u;
    if (blk < BB) {
        int b = blk, h = threadIdx.x;
        float s = 0.f;
        #pragma unroll 8
        for (int n = 0; n < NEN; n++) s += ents[(size_t)(b*NEN + n)*HH + h];
        s *= (1.0f / NEN);
        g_hx[b*HH + h] = s;
        g_cx[b*HH + h] = s;
        g_a [b*HH + h] = 0.f;
    } else {
        int i = (blk - BB)*512 + threadIdx.x;
        if (i < NROWS) g_rowsum[i] = 0.f;
    }
}

__global__ __launch_bounds__(256) void k_cvtw(const float* __restrict__ W) {
    size_t i = ((size_t)blockIdx.x*256 + threadIdx.x)*4;
    float4 v = *(const float4*)&W[i];
    __nv_bfloat162 p0 = __nv_bfloat162(__float2bfloat16(v.x), __float2bfloat16(v.y));
    __nv_bfloat162 p1 = __nv_bfloat162(__float2bfloat16(v.z), __float2bfloat16(v.w));
    *(__nv_bfloat162*)&g_Wb[i]   = p0;
    *(__nv_bfloat162*)&g_Wb[i+2] = p1;
}

// generic fp32 SGEMM: C[M,N] = A[M,K]@Bm[N,K]^T + bias
__global__ __launch_bounds__(256) void k_sgemm(
    const float* __restrict__ A, const float* __restrict__ Bm,
    const float* __restrict__ bias, float* __restrict__ C, int Kdim, int ldc)
{
    __shared__ float As[16][128];
    __shared__ float Bs[16][128];
    int m0 = blockIdx.y * 128, n0 = blockIdx.x * 128;
    int tid = threadIdx.x;
    int tx = tid & 15, ty = tid >> 4;
    int lr = tid >> 2, lc = tid & 3;
    float acc[8][8];
    #pragma unroll
    for (int i = 0; i < 8; i++)
        #pragma unroll
        for (int j = 0; j < 8; j++) acc[i][j] = 0.f;

    for (int k0 = 0; k0 < Kdim; k0 += 16) {
        #pragma unroll
        for (int i = 0; i < 2; i++) {
            float4 a4 = *(const float4*)&A[(size_t)(m0 + lr + 64*i)*Kdim + k0 + lc*4];
            As[lc*4+0][lr+64*i] = a4.x; As[lc*4+1][lr+64*i] = a4.y;
            As[lc*4+2][lr+64*i] = a4.z; As[lc*4+3][lr+64*i] = a4.w;
            float4 b4 = *(const float4*)&Bm[(size_t)(n0 + lr + 64*i)*Kdim + k0 + lc*4];
            Bs[lc*4+0][lr+64*i] = b4.x; Bs[lc*4+1][lr+64*i] = b4.y;
            Bs[lc*4+2][lr+64*i] = b4.z; Bs[lc*4+3][lr+64*i] = b4.w;
        }
        __syncthreads();
        #pragma unroll
        for (int kk = 0; kk < 16; kk++) {
            float a[8], b[8];
            *(float4*)&a[0] = *(const float4*)&As[kk][ty*8];
            *(float4*)&a[4] = *(const float4*)&As[kk][ty*8+4];
            *(float4*)&b[0] = *(const float4*)&Bs[kk][tx*8];
            *(float4*)&b[4] = *(const float4*)&Bs[kk][tx*8+4];
            #pragma unroll
            for (int i = 0; i < 8; i++)
                #pragma unroll
                for (int j = 0; j < 8; j++)
                    acc[i][j] = fmaf(a[i], b[j], acc[i][j]);
        }
        __syncthreads();
    }
    #pragma unroll
    for (int i = 0; i < 8; i++) {
        int m = m0 + ty*8 + i;
        #pragma unroll
        for (int jv = 0; jv < 2; jv++) {
            int n = n0 + tx*8 + jv*4;
            float4 v;
            v.x = acc[i][jv*4+0]; v.y = acc[i][jv*4+1];
            v.z = acc[i][jv*4+2]; v.w = acc[i][jv*4+3];
            if (bias) {
                float4 bv = *(const float4*)&bias[n];
                v.x += bv.x; v.y += bv.y; v.z += bv.z; v.w += bv.w;
            }
            *(float4*)&C[(size_t)m*ldc + n] = v;
        }
    }
}

// ---------------- bf16 tensor-core logits GEMM + fused exp-rowsum ------------
#define PADK 40

__device__ __forceinline__ void ldsm4(uint32_t& r0, uint32_t& r1, uint32_t& r2, uint32_t& r3, uint32_t addr) {
    asm volatile("ldmatrix.sync.aligned.m8n8.x4.shared.b16 {%0,%1,%2,%3}, [%4];"
                 : "=r"(r0), "=r"(r1), "=r"(r2), "=r"(r3) : "r"(addr));
}
__device__ __forceinline__ void mma16816(float* c, const uint32_t* a, const uint32_t* b) {
    asm volatile("mma.sync.aligned.m16n8k16.row.col.f32.bf16.bf16.f32 "
                 "{%0,%1,%2,%3}, {%4,%5,%6,%7}, {%8,%9}, {%0,%1,%2,%3};"
                 : "+f"(c[0]), "+f"(c[1]), "+f"(c[2]), "+f"(c[3])
                 : "r"(a[0]), "r"(a[1]), "r"(a[2]), "r"(a[3]), "r"(b[0]), "r"(b[1]));
}

__global__ __launch_bounds__(256) void k_logits_mma(
    const float* __restrict__ bias, float* __restrict__ C)
{
    __shared__ __nv_bfloat16 As[2][128*PADK];
    __shared__ __nv_bfloat16 Bs[2][128*PADK];
    __shared__ float rsum[128];
    const int Kd = 1024;
    const __nv_bfloat16* A = g_lb;
    const __nv_bfloat16* B = g_Wb;
    int m0 = blockIdx.y*128, n0 = blockIdx.x*128;
    int tid = threadIdx.x;
    int warp = tid >> 5, lane = tid & 31;
    int wm = warp >> 2, wn = warp & 3;

    int srow = tid & 127;
    int shalf = tid >> 7;
    const __nv_bfloat16* gA = A + (size_t)(m0 + srow)*Kd + shalf*16;
    const __nv_bfloat16* gB = B + (size_t)(n0 + srow)*Kd + shalf*16;
    uint32_t sA0 = (uint32_t)__cvta_generic_to_shared(&As[0][srow*PADK + shalf*16]);
    uint32_t sB0 = (uint32_t)__cvta_generic_to_shared(&Bs[0][srow*PADK + shalf*16]);
    const uint32_t bufstrideA = (uint32_t)((char*)&As[1][0] - (char*)&As[0][0]);
    const uint32_t bufstrideB = (uint32_t)((char*)&Bs[1][0] - (char*)&Bs[0][0]);

    float acc[4][4][4];
    #pragma unroll
    for (int i = 0; i < 4; i++)
        #pragma unroll
        for (int j = 0; j < 4; j++)
            #pragma unroll
            for (int k = 0; k < 4; k++) acc[i][j][k] = 0.f;

    int aq = lane >> 3;
    int arow_off = ((aq & 1) << 3) + (lane & 7);
    int acol_off = (aq >> 1) << 3;
    int brow_off = ((aq >> 1) << 3) + (lane & 7);
    int bcol_off = (aq & 1) << 3;

    #pragma unroll
    for (int s = 0; s < 2; s++) {
        asm volatile("cp.async.cg.shared.global [%0], [%1], 16;" ::
                     "r"(sA0 + s*16), "l"(gA + s*8));
        asm volatile("cp.async.cg.shared.global [%0], [%1], 16;" ::
                     "r"(sB0 + s*16), "l"(gB + s*8));
    }
    asm volatile("cp.async.commit_group;");

    const int NIT = Kd/32;
    for (int it = 0; it < NIT; it++) {
        int buf = it & 1;
        if (it + 1 < NIT) {
            uint32_t sa = sA0 + ((it+1)&1)*bufstrideA;
            uint32_t sb = sB0 + ((it+1)&1)*bufstrideB;
            const __nv_bfloat16* ga = gA + (it+1)*32;
            const __nv_bfloat16* gb = gB + (it+1)*32;
            #pragma unroll
            for (int s = 0; s < 2; s++) {
                asm volatile("cp.async.cg.shared.global [%0], [%1], 16;" ::
                             "r"(sa + s*16), "l"(ga + s*8));
                asm volatile("cp.async.cg.shared.global [%0], [%1], 16;" ::
                             "r"(sb + s*16), "l"(gb + s*8));
            }
            asm volatile("cp.async.commit_group;");
            asm volatile("cp.async.wait_group 1;");
        } else {
            asm volatile("cp.async.wait_group 0;");
        }
        __syncthreads();

        #pragma unroll
        for (int kk = 0; kk < 2; kk++) {
            uint32_t aF[4][4], bF[4][2];
            #pragma unroll
            for (int mi = 0; mi < 4; mi++) {
                int row = wm*64 + mi*16 + arow_off;
                int col = kk*16 + acol_off;
                uint32_t ad = (uint32_t)__cvta_generic_to_shared(&As[buf][row*PADK + col]);
                ldsm4(aF[mi][0], aF[mi][1], aF[mi][2], aF[mi][3], ad);
            }
            #pragma unroll
            for (int np = 0; np < 2; np++) {
                int row = wn*32 + np*16 + brow_off;
                int col = kk*16 + bcol_off;
                uint32_t bd = (uint32_t)__cvta_generic_to_shared(&Bs[buf][row*PADK + col]);
                ldsm4(bF[np*2][0], bF[np*2][1], bF[np*2+1][0], bF[np*2+1][1], bd);
            }
            #pragma unroll
            for (int mi = 0; mi < 4; mi++)
                #pragma unroll
                for (int ni = 0; ni < 4; ni++)
                    mma16816(acc[mi][ni], aF[mi], bF[ni]);
        }
        __syncthreads();
    }

    if (tid < 128) rsum[tid] = 0.f;
    __syncthreads();

    int g = lane >> 2, tg = lane & 3;
    #pragma unroll
    for (int mi = 0; mi < 4; mi++) {
        int r0l = wm*64 + mi*16 + g;
        int r1l = r0l + 8;
        float rp0 = 0.f, rp1 = 0.f;
        #pragma unroll
        for (int ni = 0; ni < 4; ni++) {
            int n = n0 + wn*32 + ni*8 + tg*2;
            float2 bv = *(const float2*)&bias[n];
            float v0 = acc[mi][ni][0] + bv.x;
            float v1 = acc[mi][ni][1] + bv.y;
            float v2 = acc[mi][ni][2] + bv.x;
            float v3 = acc[mi][ni][3] + bv.y;
            float2 w0; w0.x = v0; w0.y = v1;
            float2 w1; w1.x = v2; w1.y = v3;
            *(float2*)&C[(size_t)(m0 + r0l)*LDO + n] = w0;
            *(float2*)&C[(size_t)(m0 + r1l)*LDO + n] = w1;
            rp0 += fexp(v0) + fexp(v1);
            rp1 += fexp(v2) + fexp(v3);
        }
        atomicAdd(&rsum[r0l], rp0);
        atomicAdd(&rsum[r1l], rp1);
    }
    __syncthreads();
    if (tid < 128) atomicAdd(&g_rowsum[m0 + tid], rsum[tid]);
}

// ---------------- persistent recurrence kernel -------------------------------
__device__ __forceinline__ void gbar(unsigned target) {
    __syncthreads();
    if (threadIdx.x == 0) {
        __threadfence();
        atomicAdd(&g_barcnt, 1u);
        unsigned v;
        do {
            asm volatile("ld.acquire.gpu.u32 %0, [%1];" : "=r"(v) : "l"(&g_barcnt) : "memory");
        } while (v < target);
    }
    __syncthreads();
}

__global__ __launch_bounds__(256) void k_recur(
    const float* __restrict__ W_ih, const float* __restrict__ W_hh,
    const float* __restrict__ b_ih, const float* __restrict__ b_hh,
    const float* __restrict__ Wq, const float* __restrict__ emb,
    const int* __restrict__ outp, const int* __restrict__ entlens)
{
    extern __shared__ float sx[];                 // [8][1536] + gsh[128]
    float* gsh = sx + 8*1536;
    __shared__ float cxs[32];
    __shared__ float hxs[HH];
    __shared__ float qs[HD];
    __shared__ float sc[NEN];

    int tid = threadIdx.x;
    int blk = blockIdx.x;
    int warp = tid >> 5, lane = tid & 31;
    int hbase = blk << 2;

    if (tid < 32) {
        int hh2 = tid >> 3, b = tid & 7;
        cxs[tid] = g_cx[b*HH + hbase + hh2];
    }

    int rl0 = warp*2, rl1 = rl0 + 1;
    int r0 = (rl0 >> 2)*512 + hbase + (rl0 & 3);
    int r1 = (rl1 >> 2)*512 + hbase + (rl1 & 3);
    const float4* wa0 = (const float4*)(W_ih + (size_t)r0*1024);
    const float4* wa1 = (const float4*)(W_ih + (size_t)r1*1024);
    const float4* wb0 = (const float4*)(W_hh + (size_t)r0*512);
    const float4* wb1 = (const float4*)(W_hh + (size_t)r1*512);
    float bias0 = b_ih[r0] + b_hh[r0];
    float bias1 = b_ih[r1] + b_hh[r1];

    unsigned target = GRIDN;

    for (int t = 0; t < TT; t++) {
        // ---------- phase 1: gates + cell update (all blocks) ----------
        for (int i = tid; i < BB*HH; i += 256) {
            int b = i >> 9, j = i & 511;
            sx[b*1536 + j]        = __ldcg(&g_a[i]);
            sx[b*1536 + 1024 + j] = __ldcg(&g_hx[i]);
            sx[b*1536 + 512  + j] = __ldg(&emb[(size_t)__ldg(&outp[b*TT + t])*HH + j]);
        }
        __syncthreads();

        float acc0[8], acc1[8];
        #pragma unroll
        for (int b = 0; b < 8; b++) { acc0[b] = 0.f; acc1[b] = 0.f; }

        #pragma unroll
        for (int i = 0; i < 8; i++) {
            float4 w0 = wa0[i*32 + lane];
            float4 w1 = wa1[i*32 + lane];
            #pragma unroll
            for (int b = 0; b < 8; b++) {
                float4 x = *(const float4*)&sx[b*1536 + ((i*32 + lane) << 2)];
                acc0[b] = fmaf(w0.x,x.x, fmaf(w0.y,x.y, fmaf(w0.z,x.z, fmaf(w0.w,x.w, acc0[b]))));
                acc1[b] = fmaf(w1.x,x.x, fmaf(w1.y,x.y, fmaf(w1.z,x.z, fmaf(w1.w,x.w, acc1[b]))));
            }
        }
        #pragma unroll
        for (int i = 0; i < 4; i++) {
            float4 w0 = wb0[i*32 + lane];
            float4 w1 = wb1[i*32 + lane];
            #pragma unroll
            for (int b = 0; b < 8; b++) {
                float4 x = *(const float4*)&sx[b*1536 + 1024 + ((i*32 + lane) << 2)];
                acc0[b] = fmaf(w0.x,x.x, fmaf(w0.y,x.y, fmaf(w0.z,x.z, fmaf(w0.w,x.w, acc0[b]))));
                acc1[b] = fmaf(w1.x,x.x, fmaf(w1.y,x.y, fmaf(w1.z,x.z, fmaf(w1.w,x.w, acc1[b]))));
            }
        }
        #pragma unroll
        for (int b = 0; b < 8; b++) {
            float v0 = acc0[b], v1 = acc1[b];
            #pragma unroll
            for (int o = 16; o; o >>= 1) {
                v0 += __shfl_xor_sync(0xffffffffu, v0, o);
                v1 += __shfl_xor_sync(0xffffffffu, v1, o);
            }
            if (lane == 0) {
                gsh[rl0*8 + b] = v0 + bias0;
                gsh[rl1*8 + b] = v1 + bias1;
            }
        }
        __syncthreads();
        if (tid < 32) {
            int hh2 = tid >> 3, b = tid & 7;
            int h = hbase + hh2;
            float gi = gsh[(     hh2)*8 + b];
            float gf = gsh[( 4 + hh2)*8 + b];
            float gg = gsh[( 8 + hh2)*8 + b];
            float go = gsh[(12 + hh2)*8 + b];
            float c  = sigf(gf)*cxs[tid] + sigf(gi)*tanhf(gg);
            float hx = sigf(go)*tanhf(c);
            cxs[tid] = c;
            g_hx[b*HH + h] = hx;
            size_t li = ((size_t)(b*TT + t))*1024 + h;
            g_l[li]  = hx;
            g_lb[li] = __float2bfloat16(hx);
        }

        gbar(target); target += GRIDN;

        // ---------- phase 2: MHA (blocks 0-31) ----------
        if (blk < 32) {
            int b = blk >> 2, hd4 = blk & 3;
            for (int i = tid; i < HH; i += 256) hxs[i] = __ldcg(&g_hx[b*HH + i]);
            __syncthreads();
            if (tid < HD) {
                float acc = 0.f;
                const float4* w4 = (const float4*)(Wq + (size_t)(hd4*HD + tid)*HH);
                const float4* x4 = (const float4*)hxs;
                #pragma unroll 16
                for (int i = 0; i < HH/4; i++) {
                    float4 w = w4[i], x = x4[i];
                    acc = fmaf(w.x,x.x, fmaf(w.y,x.y, fmaf(w.z,x.z, fmaf(w.w,x.w, acc))));
                }
                qs[tid] = acc;
            }
            __syncthreads();
            int len = __ldg(&entlens[b]);
            if (tid < NEN) {
                float sv = -1e30f;
                if (tid <= len) {
                    float acc = 0.f;
                    const float4* k4 = (const float4*)(g_K + (size_t)(b*NEN + tid)*HH + hd4*HD);
                    const float4* q4 = (const float4*)qs;
                    #pragma unroll 8
                    for (int i = 0; i < HD/4; i++) {
                        float4 kv = k4[i], qv = q4[i];
                        acc = fmaf(kv.x,qv.x, fmaf(kv.y,qv.y, fmaf(kv.z,qv.z, fmaf(kv.w,qv.w, acc))));
                    }
                    sv = acc * 0.04419417382415922f;   // 1/sqrt(512)
                }
                sc[tid] = sv;
            }
            __syncthreads();
            if (tid < 32) {
                float v0 = sc[tid], v1 = sc[tid+32];
                float m = fmaxf(v0, v1);
                #pragma unroll
                for (int o = 16; o; o >>= 1) m = fmaxf(m, __shfl_xor_sync(0xffffffffu, m, o));
                float e0 = __expf(v0 - m), e1 = __expf(v1 - m);
                float s2 = e0 + e1;
                #pragma unroll
                for (int o = 16; o; o >>= 1) s2 += __shfl_xor_sync(0xffffffffu, s2, o);
                float inv = 1.0f / s2;
                sc[tid]      = e0 * inv;
                sc[tid + 32] = e1 * inv;
            }
            __syncthreads();
            if (tid < HD) {
                float acc = 0.f;
                const float* vb = g_V + (size_t)b*NEN*HH + hd4*HD + tid;
                #pragma unroll 8
                for (int n = 0; n < NEN; n++) acc = fmaf(sc[n], __ldg(&vb[(size_t)n*HH]), acc);
                int h = hd4*HD + tid;
                g_a[b*HH + h] = acc;
                size_t li = ((size_t)(b*TT + t))*1024 + 512 + h;
                g_l[li]  = acc;
                g_lb[li] = __float2bfloat16(acc);
            }
        }

        gbar(target); target += GRIDN;
    }
}

__global__ __launch_bounds__(256) void k_switch(
    const float* __restrict__ sw_W, const float* __restrict__ sw_b)
{
    int r = blockIdx.x*8 + (threadIdx.x >> 5);
    int lane = threadIdx.x & 31;
    const float4* l4 = (const float4*)(g_l + (size_t)r*1024);
    const float4* w4 = (const float4*)sw_W;
    float acc = 0.f;
    #pragma unroll
    for (int i = 0; i < 8; i++) {
        float4 a = l4[i*32 + lane], w = w4[i*32 + lane];
        acc = fmaf(a.x,w.x, fmaf(a.y,w.y, fmaf(a.z,w.z, fmaf(a.w,w.w, acc))));
    }
    #pragma unroll
    for (int o = 16; o; o >>= 1) acc += __shfl_xor_sync(0xffffffffu, acc, o);
    if (lane == 0) g_s[r] = sigf(acc + sw_b[0]);
}

__global__ __launch_bounds__(64) void k_ptr(
    const float* __restrict__ ents, const int* __restrict__ entlens,
    float* __restrict__ out, int write_tail)
{
    __shared__ float ds[HH];
    __shared__ float red[2];
    int r = blockIdx.x;
    int b = r >> 8;
    int tid = threadIdx.x;
    for (int i = tid; i < HH; i += 64) ds[i] = g_dec[(size_t)r*HH + i];
    __syncthreads();
    int len = entlens[b];
    float sv = -1e30f;
    if (tid <= len) {
        float acc = 0.f;
        const float4* e4 = (const float4*)(ents + (size_t)(b*NEN + tid)*HH);
        const float4* d4 = (const float4*)ds;
        #pragma unroll 8
        for (int i = 0; i < HH/4; i++) {
            float4 ev = e4[i], dv = d4[i];
            acc = fmaf(ev.x,dv.x, fmaf(ev.y,dv.y, fmaf(ev.z,dv.z, fmaf(ev.w,dv.w, acc))));
        }
        sv = acc;
    }
    float v = sv;
    #pragma unroll
    for (int o = 16; o; o >>= 1) v = fmaxf(v, __shfl_xor_sync(0xffffffffu, v, o));
    if ((tid & 31) == 0) red[tid >> 5] = v;
    __syncthreads();
    float m = fmaxf(red[0], red[1]);
    float e = (tid <= len) ? __expf(sv - m) : 0.f;
    float s2 = e;
    #pragma unroll
    for (int o = 16; o; o >>= 1) s2 += __shfl_xor_sync(0xffffffffu, s2, o);
    if ((tid & 31) == 0) red[tid >> 5] = s2;
    __syncthreads();
    float inv = 1.0f / (red[0] + red[1]);
    float s = g_s[r];
    float z = e * inv * (1.0f - s);
    out[(size_t)r*LDO + VOCAB + tid] = __logf(z + 1e-6f);
    if (write_tail) out[(size_t)NROWS*LDO + (size_t)r*NEN + tid] = z;
}

__global__ void k_rowc() {
    int r = blockIdx.x*256 + threadIdx.x;
    if (r < NROWS) g_c[r] = g_s[r] / g_rowsum[r];
}

__global__ __launch_bounds__(256) void k_final(float* __restrict__ out) {
    int r = blockIdx.x;
    float c = g_c[r];
    float4* row = (float4*)(out + (size_t)r*LDO);
    for (int i = threadIdx.x; i < VOCAB/4; i += 256) {
        float4 v = row[i];
        v.x = __logf(fmaf(fexp(v.x), c, 1e-6f));
        v.y = __logf(fmaf(fexp(v.y), c, 1e-6f));
        v.z = __logf(fmaf(fexp(v.z), c, 1e-6f));
        v.w = __logf(fmaf(fexp(v.w), c, 1e-6f));
        row[i] = v;
    }
}

extern "C" void kernel_launch(void* const* d_in, const int* in_sizes, int n_in,
                              void* d_out, int out_size)
{
    const int*   outp    = (const int*)  d_in[0];
    const float* ents    = (const float*)d_in[1];
    const int*   entlens = (const int*)  d_in[2];
    const float* emb     = (const float*)d_in[3];
    const float* W_ih    = (const float*)d_in[4];
    const float* W_hh    = (const float*)d_in[5];
    const float* b_ih    = (const float*)d_in[6];
    const float* b_hh    = (const float*)d_in[7];
    const float* Wq      = (const float*)d_in[8];
    const float* Wk      = (const float*)d_in[9];
    const float* Wv      = (const float*)d_in[10];
    const float* out_W   = (const float*)d_in[11];
    const float* out_b   = (const float*)d_in[12];
    const float* sw_W    = (const float*)d_in[13];
    const float* sw_b    = (const float*)d_in[14];
    const float* mattn_W = (const float*)d_in[15];
    const float* mattn_b = (const float*)d_in[16];
    float* out = (float*)d_out;

    static int smem_set = 0;
    if (!smem_set) {
        cudaFuncSetAttribute(k_recur, cudaFuncAttributeMaxDynamicSharedMemorySize, 64*1024);
        smem_set = 1;
    }
    const int recur_smem = (8*1536 + 128) * 4;

    float *g_K_p, *g_V_p, *g_l_p, *g_dec_p;
    cudaGetSymbolAddress((void**)&g_K_p, g_K);
    cudaGetSymbolAddress((void**)&g_V_p, g_V);
    cudaGetSymbolAddress((void**)&g_l_p, g_l);
    cudaGetSymbolAddress((void**)&g_dec_p, g_dec);

    k_init<<<12, 512>>>(ents);
    k_cvtw<<<VOCAB*1024/(256*4), 256>>>(out_W);
    k_sgemm<<<dim3(4,4), 256>>>(ents, Wk, nullptr, g_K_p, 512, 512);
    k_sgemm<<<dim3(4,4), 256>>>(ents, Wv, nullptr, g_V_p, 512, 512);

    k_recur<<<GRIDN, 256, recur_smem>>>(W_ih, W_hh, b_ih, b_hh, Wq, emb, outp, entlens);

    k_switch<<<NROWS/8, 256>>>(sw_W, sw_b);
    k_sgemm<<<dim3(4,16), 256>>>(g_l_p, mattn_W, mattn_b, g_dec_p, 1024, 512);
    k_logits_mma<<<dim3(VOCAB/128, NROWS/128), 256>>>(out_b, out);
    k_rowc<<<8, 256>>>();
    int write_tail = (out_size >= NROWS*LDO + NROWS*NEN) ? 1 : 0;
    k_ptr<<<NROWS, 64>>>(ents, entlens, out, write_tail);
    k_final<<<NROWS, 256>>>(out);
}

// round 6
// speedup vs baseline: 1.9583x; 1.2313x over previous
#include <cuda_runtime.h>
#include <cuda_bf16.h>
#include <cstdint>
#include <cstddef>

#define BB     8
#define TT     256
#define NEN    64
#define HH     512
#define HD     128
#define VOCAB  32000
#define NROWS  (BB*TT)
#define LDO    (VOCAB+NEN)
#define GRIDN  128

__device__ float g_K[BB*NEN*HH];
__device__ float g_V[BB*NEN*HH];
__device__ float g_P[4*512*HH];          // P[h][(b*64+n)][j]
__device__ float g_Wqt[HH*HH];           // Wq transposed
__device__ float g_hx[BB*HH];
__device__ float g_cx[BB*HH];
__device__ float g_a[BB*HH];
__device__ float g_l[(size_t)NROWS*2*HH];
__device__ float g_dec[(size_t)NROWS*HH];
__device__ float g_s[NROWS];
__device__ float g_rowsum[NROWS];
__device__ float g_c[NROWS];
__device__ unsigned g_c1, g_c2;
__device__ __nv_bfloat16 g_Wb[(size_t)VOCAB*1024];
__device__ __nv_bfloat16 g_lb[(size_t)NROWS*1024];
__device__ __nv_bfloat16 g_logb[(size_t)NROWS*VOCAB];

__device__ __forceinline__ float sigf(float x) { return 1.0f / (1.0f + __expf(-x)); }

__device__ __forceinline__ float fexp(float x) {
    float z = x * 1.44269504088896f;
    float r = z + 12582912.0f;
    int   n = __float_as_int(r) - 0x4B400000;
    float f = z - (r - 12582912.0f);
    float p = 1.33336498e-3f;
    p = fmaf(p, f, 9.61011474e-3f);
    p = fmaf(p, f, 5.55036190e-2f);
    p = fmaf(p, f, 2.40226337e-1f);
    p = fmaf(p, f, 6.93147182e-1f);
    p = fmaf(p, f, 1.0f);
    return p * __int_as_float((n + 127) << 23);
}

__device__ __forceinline__ void red_add(unsigned* p) {
    asm volatile("red.release.gpu.global.add.u32 [%0], 1;" :: "l"(p) : "memory");
}
__device__ __forceinline__ unsigned ld_acq(unsigned* p) {
    unsigned v;
    asm volatile("ld.acquire.gpu.global.u32 %0, [%1];" : "=r"(v) : "l"(p) : "memory");
    return v;
}

__global__ void k_init(const float* __restrict__ ents) {
    int blk = blockIdx.x;
    if (blk == 0 && threadIdx.x == 0) { g_c1 = 0u; g_c2 = 0u; }
    if (blk < BB) {
        int b = blk, h = threadIdx.x;
        float s = 0.f;
        #pragma unroll 8
        for (int n = 0; n < NEN; n++) s += ents[(size_t)(b*NEN + n)*HH + h];
        s *= (1.0f / NEN);
        g_hx[b*HH + h] = s;
        g_cx[b*HH + h] = s;
        g_a [b*HH + h] = 0.f;
    } else {
        int i = (blk - BB)*512 + threadIdx.x;
        if (i < NROWS) g_rowsum[i] = 0.f;
    }
}

__global__ __launch_bounds__(256) void k_cvtw(const float* __restrict__ W) {
    size_t i = ((size_t)blockIdx.x*256 + threadIdx.x)*4;
    float4 v = *(const float4*)&W[i];
    __nv_bfloat162 p0 = __nv_bfloat162(__float2bfloat16(v.x), __float2bfloat16(v.y));
    __nv_bfloat162 p1 = __nv_bfloat162(__float2bfloat16(v.z), __float2bfloat16(v.w));
    *(__nv_bfloat162*)&g_Wb[i]   = p0;
    *(__nv_bfloat162*)&g_Wb[i+2] = p1;
}

__global__ void k_transp(const float* __restrict__ Wq) {
    __shared__ float t[32][33];
    int bx = blockIdx.x*32, by = blockIdx.y*32;
    int x = threadIdx.x, y = threadIdx.y;   // 32 x 8
    #pragma unroll
    for (int i = 0; i < 32; i += 8)
        t[y+i][x] = Wq[(size_t)(by + y + i)*HH + bx + x];
    __syncthreads();
    #pragma unroll
    for (int i = 0; i < 32; i += 8)
        g_Wqt[(size_t)(bx + y + i)*HH + by + x] = t[x][y+i];
}

// generic fp32 SGEMM: C[M,N] = A[M,K]@Bm[N,K]^T + bias, with z-batch offsets
__global__ __launch_bounds__(256) void k_sgemm(
    const float* __restrict__ A, int lda, int zA,
    const float* __restrict__ Bm, int ldb, int zB,
    const float* __restrict__ bias, float* __restrict__ C, int ldc, int zC,
    int Kdim)
{
    __shared__ float As[16][128];
    __shared__ float Bs[16][128];
    const float* Ab = A + (size_t)blockIdx.z*zA;
    const float* Bb = Bm + (size_t)blockIdx.z*zB;
    float* Cb = C + (size_t)blockIdx.z*zC;
    int m0 = blockIdx.y * 128, n0 = blockIdx.x * 128;
    int tid = threadIdx.x;
    int tx = tid & 15, ty = tid >> 4;
    int lr = tid >> 2, lc = tid & 3;
    float acc[8][8];
    #pragma unroll
    for (int i = 0; i < 8; i++)
        #pragma unroll
        for (int j = 0; j < 8; j++) acc[i][j] = 0.f;

    for (int k0 = 0; k0 < Kdim; k0 += 16) {
        #pragma unroll
        for (int i = 0; i < 2; i++) {
            float4 a4 = *(const float4*)&Ab[(size_t)(m0 + lr + 64*i)*lda + k0 + lc*4];
            As[lc*4+0][lr+64*i] = a4.x; As[lc*4+1][lr+64*i] = a4.y;
            As[lc*4+2][lr+64*i] = a4.z; As[lc*4+3][lr+64*i] = a4.w;
            float4 b4 = *(const float4*)&Bb[(size_t)(n0 + lr + 64*i)*ldb + k0 + lc*4];
            Bs[lc*4+0][lr+64*i] = b4.x; Bs[lc*4+1][lr+64*i] = b4.y;
            Bs[lc*4+2][lr+64*i] = b4.z; Bs[lc*4+3][lr+64*i] = b4.w;
        }
        __syncthreads();
        #pragma unroll
        for (int kk = 0; kk < 16; kk++) {
            float a[8], b[8];
            *(float4*)&a[0] = *(const float4*)&As[kk][ty*8];
            *(float4*)&a[4] = *(const float4*)&As[kk][ty*8+4];
            *(float4*)&b[0] = *(const float4*)&Bs[kk][tx*8];
            *(float4*)&b[4] = *(const float4*)&Bs[kk][tx*8+4];
            #pragma unroll
            for (int i = 0; i < 8; i++)
                #pragma unroll
                for (int j = 0; j < 8; j++)
                    acc[i][j] = fmaf(a[i], b[j], acc[i][j]);
        }
        __syncthreads();
    }
    #pragma unroll
    for (int i = 0; i < 8; i++) {
        int m = m0 + ty*8 + i;
        #pragma unroll
        for (int jv = 0; jv < 2; jv++) {
            int n = n0 + tx*8 + jv*4;
            float4 v;
            v.x = acc[i][jv*4+0]; v.y = acc[i][jv*4+1];
            v.z = acc[i][jv*4+2]; v.w = acc[i][jv*4+3];
            if (bias) {
                float4 bv = *(const float4*)&bias[n];
                v.x += bv.x; v.y += bv.y; v.z += bv.z; v.w += bv.w;
            }
            *(float4*)&Cb[(size_t)m*ldc + n] = v;
        }
    }
}

// ---------------- bf16 tensor-core logits GEMM + fused exp-rowsum ------------
#define PADK 40

__device__ __forceinline__ void ldsm4(uint32_t& r0, uint32_t& r1, uint32_t& r2, uint32_t& r3, uint32_t addr) {
    asm volatile("ldmatrix.sync.aligned.m8n8.x4.shared.b16 {%0,%1,%2,%3}, [%4];"
                 : "=r"(r0), "=r"(r1), "=r"(r2), "=r"(r3) : "r"(addr));
}
__device__ __forceinline__ void mma16816(float* c, const uint32_t* a, const uint32_t* b) {
    asm volatile("mma.sync.aligned.m16n8k16.row.col.f32.bf16.bf16.f32 "
                 "{%0,%1,%2,%3}, {%4,%5,%6,%7}, {%8,%9}, {%0,%1,%2,%3};"
                 : "+f"(c[0]), "+f"(c[1]), "+f"(c[2]), "+f"(c[3])
                 : "r"(a[0]), "r"(a[1]), "r"(a[2]), "r"(a[3]), "r"(b[0]), "r"(b[1]));
}

__global__ __launch_bounds__(256) void k_logits_mma(const float* __restrict__ bias)
{
    __shared__ __nv_bfloat16 As[2][128*PADK];
    __shared__ __nv_bfloat16 Bs[2][128*PADK];
    __shared__ float rsum[128];
    const int Kd = 1024;
    const __nv_bfloat16* A = g_lb;
    const __nv_bfloat16* B = g_Wb;
    int m0 = blockIdx.y*128, n0 = blockIdx.x*128;
    int tid = threadIdx.x;
    int warp = tid >> 5, lane = tid & 31;
    int wm = warp >> 2, wn = warp & 3;

    int srow = tid & 127;
    int shalf = tid >> 7;
    const __nv_bfloat16* gA = A + (size_t)(m0 + srow)*Kd + shalf*16;
    const __nv_bfloat16* gB = B + (size_t)(n0 + srow)*Kd + shalf*16;
    uint32_t sA0 = (uint32_t)__cvta_generic_to_shared(&As[0][srow*PADK + shalf*16]);
    uint32_t sB0 = (uint32_t)__cvta_generic_to_shared(&Bs[0][srow*PADK + shalf*16]);
    const uint32_t bufstrideA = (uint32_t)((char*)&As[1][0] - (char*)&As[0][0]);
    const uint32_t bufstrideB = (uint32_t)((char*)&Bs[1][0] - (char*)&Bs[0][0]);

    float acc[4][4][4];
    #pragma unroll
    for (int i = 0; i < 4; i++)
        #pragma unroll
        for (int j = 0; j < 4; j++)
            #pragma unroll
            for (int k = 0; k < 4; k++) acc[i][j][k] = 0.f;

    int aq = lane >> 3;
    int arow_off = ((aq & 1) << 3) + (lane & 7);
    int acol_off = (aq >> 1) << 3;
    int brow_off = ((aq >> 1) << 3) + (lane & 7);
    int bcol_off = (aq & 1) << 3;

    #pragma unroll
    for (int s = 0; s < 2; s++) {
        asm volatile("cp.async.cg.shared.global [%0], [%1], 16;" ::
                     "r"(sA0 + s*16), "l"(gA + s*8));
        asm volatile("cp.async.cg.shared.global [%0], [%1], 16;" ::
                     "r"(sB0 + s*16), "l"(gB + s*8));
    }
    asm volatile("cp.async.commit_group;");

    const int NIT = Kd/32;
    for (int it = 0; it < NIT; it++) {
        int buf = it & 1;
        if (it + 1 < NIT) {
            uint32_t sa = sA0 + ((it+1)&1)*bufstrideA;
            uint32_t sb = sB0 + ((it+1)&1)*bufstrideB;
            const __nv_bfloat16* ga = gA + (it+1)*32;
            const __nv_bfloat16* gb = gB + (it+1)*32;
            #pragma unroll
            for (int s = 0; s < 2; s++) {
                asm volatile("cp.async.cg.shared.global [%0], [%1], 16;" ::
                             "r"(sa + s*16), "l"(ga + s*8));
                asm volatile("cp.async.cg.shared.global [%0], [%1], 16;" ::
                             "r"(sb + s*16), "l"(gb + s*8));
            }
            asm volatile("cp.async.commit_group;");
            asm volatile("cp.async.wait_group 1;");
        } else {
            asm volatile("cp.async.wait_group 0;");
        }
        __syncthreads();

        #pragma unroll
        for (int kk = 0; kk < 2; kk++) {
            uint32_t aF[4][4], bF[4][2];
            #pragma unroll
            for (int mi = 0; mi < 4; mi++) {
                int row = wm*64 + mi*16 + arow_off;
                int col = kk*16 + acol_off;
                uint32_t ad = (uint32_t)__cvta_generic_to_shared(&As[buf][row*PADK + col]);
                ldsm4(aF[mi][0], aF[mi][1], aF[mi][2], aF[mi][3], ad);
            }
            #pragma unroll
            for (int np = 0; np < 2; np++) {
                int row = wn*32 + np*16 + brow_off;
                int col = kk*16 + bcol_off;
                uint32_t bd = (uint32_t)__cvta_generic_to_shared(&Bs[buf][row*PADK + col]);
                ldsm4(bF[np*2][0], bF[np*2][1], bF[np*2+1][0], bF[np*2+1][1], bd);
            }
            #pragma unroll
            for (int mi = 0; mi < 4; mi++)
                #pragma unroll
                for (int ni = 0; ni < 4; ni++)
                    mma16816(acc[mi][ni], aF[mi], bF[ni]);
        }
        __syncthreads();
    }

    if (tid < 128) rsum[tid] = 0.f;
    __syncthreads();

    int g = lane >> 2, tg = lane & 3;
    #pragma unroll
    for (int mi = 0; mi < 4; mi++) {
        int r0l = wm*64 + mi*16 + g;
        int r1l = r0l + 8;
        float rp0 = 0.f, rp1 = 0.f;
        #pragma unroll
        for (int ni = 0; ni < 4; ni++) {
            int n = n0 + wn*32 + ni*8 + tg*2;
            float2 bv = *(const float2*)&bias[n];
            float v0 = acc[mi][ni][0] + bv.x;
            float v1 = acc[mi][ni][1] + bv.y;
            float v2 = acc[mi][ni][2] + bv.x;
            float v3 = acc[mi][ni][3] + bv.y;
            *(__nv_bfloat162*)&g_logb[(size_t)(m0 + r0l)*VOCAB + n] =
                __nv_bfloat162(__float2bfloat16(v0), __float2bfloat16(v1));
            *(__nv_bfloat162*)&g_logb[(size_t)(m0 + r1l)*VOCAB + n] =
                __nv_bfloat162(__float2bfloat16(v2), __float2bfloat16(v3));
            rp0 += fexp(v0) + fexp(v1);
            rp1 += fexp(v2) + fexp(v3);
        }
        atomicAdd(&rsum[r0l], rp0);
        atomicAdd(&rsum[r1l], rp1);
    }
    __syncthreads();
    if (tid < 128) atomicAdd(&g_rowsum[m0 + tid], rsum[tid]);
}

// ---------------- persistent recurrence kernel -------------------------------
// blocks 0-95: LSTM gates+cell (blocks 0-31: 6 h-groups, 32-95: 5 h-groups)
// blocks 96-127: attention via L1-resident P and V slices
__global__ __launch_bounds__(256) void k_recur(
    const float* __restrict__ W_ih, const float* __restrict__ W_hh,
    const float* __restrict__ b_ih, const float* __restrict__ b_hh,
    const float* __restrict__ emb, const int* __restrict__ outp,
    const int* __restrict__ entlens)
{
    extern __shared__ float sx[];                 // [8][1536] + gsh[192]
    float* gsh = sx + 8*1536;
    __shared__ float cxs[48];
    __shared__ float hxs[HH];
    __shared__ float sc[NEN];

    int tid = threadIdx.x;
    int blk = blockIdx.x;
    int warp = tid >> 5, lane = tid & 31;
    bool isAtt = (blk >= 96);

    // phase-1 setup
    int ng = 0, g0 = 0, nrows = 0;
    const float4 *wa0=nullptr,*wa1=nullptr,*wa2=nullptr,*wb0=nullptr,*wb1=nullptr,*wb2=nullptr;
    float bias0=0.f, bias1=0.f, bias2=0.f;
    bool has2 = false;
    // phase-2 setup
    int ab = 0, ah = 0, alen = 0;

    if (!isAtt) {
        ng = (blk < 32) ? 6 : 5;
        g0 = (blk < 32) ? blk*6 : 192 + (blk - 32)*5;
        nrows = 4*ng;
        int lr0 = warp, lr1 = warp + 8, lr2 = warp + 16;
        has2 = (lr2 < nrows);
        int r0 = (lr0 & 3)*512 + g0 + (lr0 >> 2);
        int r1 = (lr1 & 3)*512 + g0 + (lr1 >> 2);
        int r2 = has2 ? ((lr2 & 3)*512 + g0 + (lr2 >> 2)) : r0;
        wa0 = (const float4*)(W_ih + (size_t)r0*1024);
        wa1 = (const float4*)(W_ih + (size_t)r1*1024);
        wa2 = (const float4*)(W_ih + (size_t)r2*1024);
        wb0 = (const float4*)(W_hh + (size_t)r0*512);
        wb1 = (const float4*)(W_hh + (size_t)r1*512);
        wb2 = (const float4*)(W_hh + (size_t)r2*512);
        bias0 = b_ih[r0] + b_hh[r0];
        bias1 = b_ih[r1] + b_hh[r1];
        bias2 = has2 ? (b_ih[r2] + b_hh[r2]) : 0.f;
        if (tid < ng*8)
            cxs[tid] = g_cx[(tid & 7)*HH + g0 + (tid >> 3)];
    } else {
        ab = (blk - 96) >> 2;
        ah = (blk - 96) & 3;
        alen = __ldg(&entlens[ab]);
    }

    unsigned t1 = GRIDN, t2 = GRIDN;

    for (int t = 0; t < TT; t++) {
        if (!isAtt) {
            // ---------- phase 1: gates + cell update ----------
            for (int i = tid; i < BB*HH; i += 256) {
                int b = i >> 9, j = i & 511;
                sx[b*1536 + j]        = __ldcg(&g_a[i]);
                sx[b*1536 + 1024 + j] = __ldcg(&g_hx[i]);
                sx[b*1536 + 512  + j] = __ldg(&emb[(size_t)__ldg(&outp[b*TT + t])*HH + j]);
            }
            __syncthreads();

            float acc0[8], acc1[8], acc2[8];
            #pragma unroll
            for (int b = 0; b < 8; b++) { acc0[b] = 0.f; acc1[b] = 0.f; acc2[b] = 0.f; }

            #pragma unroll
            for (int i = 0; i < 8; i++) {
                float4 w0 = wa0[i*32 + lane];
                float4 w1 = wa1[i*32 + lane];
                float4 w2 = wa2[i*32 + lane];
                #pragma unroll
                for (int b = 0; b < 8; b++) {
                    float4 x = *(const float4*)&sx[b*1536 + ((i*32 + lane) << 2)];
                    acc0[b] = fmaf(w0.x,x.x, fmaf(w0.y,x.y, fmaf(w0.z,x.z, fmaf(w0.w,x.w, acc0[b]))));
                    acc1[b] = fmaf(w1.x,x.x, fmaf(w1.y,x.y, fmaf(w1.z,x.z, fmaf(w1.w,x.w, acc1[b]))));
                    acc2[b] = fmaf(w2.x,x.x, fmaf(w2.y,x.y, fmaf(w2.z,x.z, fmaf(w2.w,x.w, acc2[b]))));
                }
            }
            #pragma unroll
            for (int i = 0; i < 4; i++) {
                float4 w0 = wb0[i*32 + lane];
                float4 w1 = wb1[i*32 + lane];
                float4 w2 = wb2[i*32 + lane];
                #pragma unroll
                for (int b = 0; b < 8; b++) {
                    float4 x = *(const float4*)&sx[b*1536 + 1024 + ((i*32 + lane) << 2)];
                    acc0[b] = fmaf(w0.x,x.x, fmaf(w0.y,x.y, fmaf(w0.z,x.z, fmaf(w0.w,x.w, acc0[b]))));
                    acc1[b] = fmaf(w1.x,x.x, fmaf(w1.y,x.y, fmaf(w1.z,x.z, fmaf(w1.w,x.w, acc1[b]))));
                    acc2[b] = fmaf(w2.x,x.x, fmaf(w2.y,x.y, fmaf(w2.z,x.z, fmaf(w2.w,x.w, acc2[b]))));
                }
            }
            #pragma unroll
            for (int b = 0; b < 8; b++) {
                float v0 = acc0[b], v1 = acc1[b], v2 = acc2[b];
                #pragma unroll
                for (int o = 16; o; o >>= 1) {
                    v0 += __shfl_xor_sync(0xffffffffu, v0, o);
                    v1 += __shfl_xor_sync(0xffffffffu, v1, o);
                    v2 += __shfl_xor_sync(0xffffffffu, v2, o);
                }
                if (lane == 0) {
                    gsh[warp*8 + b]        = v0 + bias0;
                    gsh[(warp+8)*8 + b]    = v1 + bias1;
                    if (has2) gsh[(warp+16)*8 + b] = v2 + bias2;
                }
            }
            __syncthreads();
            if (tid < ng*8) {
                int lg = tid >> 3, b = tid & 7;
                int h = g0 + lg;
                float gi = gsh[(lg*4 + 0)*8 + b];
                float gf = gsh[(lg*4 + 1)*8 + b];
                float gg = gsh[(lg*4 + 2)*8 + b];
                float go = gsh[(lg*4 + 3)*8 + b];
                float c  = sigf(gf)*cxs[tid] + sigf(gi)*tanhf(gg);
                float hx = sigf(go)*tanhf(c);
                cxs[tid] = c;
                g_hx[b*HH + h] = hx;
                size_t li = ((size_t)(b*TT + t))*1024 + h;
                g_l[li]  = hx;
                g_lb[li] = __float2bfloat16(hx);
            }
            __syncthreads();
            if (tid == 0) { red_add(&g_c1); red_add(&g_c2); }
            if (tid == 0) { while (ld_acq(&g_c2) < t2) __nanosleep(64); }
            __syncthreads();
        } else {
            // ---------- phase 2: attention ----------
            __syncthreads();
            if (tid == 0) red_add(&g_c1);
            if (tid == 0) { while (ld_acq(&g_c1) < t1) __nanosleep(64); }
            __syncthreads();

            for (int i = tid; i < HH; i += 256) hxs[i] = __ldcg(&g_hx[ab*HH + i]);
            __syncthreads();

            {   // scores: 64 n x 4 threads, 128-dim partial each
                int n = tid >> 2, sub = tid & 3;
                const float4* p4 = (const float4*)(g_P + ((size_t)(ah*512 + ab*64 + n))*512 + sub*128);
                const float4* x4 = (const float4*)(hxs + sub*128);
                float acc = 0.f;
                #pragma unroll 8
                for (int i = 0; i < 32; i++) {
                    float4 p = __ldg(&p4[i]), x = x4[i];
                    acc = fmaf(p.x,x.x, fmaf(p.y,x.y, fmaf(p.z,x.z, fmaf(p.w,x.w, acc))));
                }
                acc += __shfl_xor_sync(0xffffffffu, acc, 1);
                acc += __shfl_xor_sync(0xffffffffu, acc, 2);
                if (sub == 0)
                    sc[n] = (n <= alen) ? acc * 0.04419417382415922f : -1e30f;
            }
            __syncthreads();
            if (tid < 32) {
                float v0 = sc[tid], v1 = sc[tid + 32];
                float m = fmaxf(v0, v1);
                #pragma unroll
                for (int o = 16; o; o >>= 1) m = fmaxf(m, __shfl_xor_sync(0xffffffffu, m, o));
                float e0 = __expf(v0 - m), e1 = __expf(v1 - m);
                float s2 = e0 + e1;
                #pragma unroll
                for (int o = 16; o; o >>= 1) s2 += __shfl_xor_sync(0xffffffffu, s2, o);
                float inv = 1.0f / s2;
                sc[tid]      = e0 * inv;
                sc[tid + 32] = e1 * inv;
            }
            __syncthreads();
            {   // a = attn . V : 128 d x 2 halves
                int d = tid >> 1, half = tid & 1;
                const float* vb = g_V + ((size_t)(ab*64 + half*32))*512 + ah*128 + d;
                float acc = 0.f;
                #pragma unroll 8
                for (int n2 = 0; n2 < 32; n2++)
                    acc = fmaf(sc[half*32 + n2], __ldg(&vb[(size_t)n2*512]), acc);
                float other = __shfl_xor_sync(0xffffffffu, acc, 1);
                if (half == 0) {
                    float av = acc + other;
                    int h = ah*128 + d;
                    g_a[ab*HH + h] = av;
                    size_t li = ((size_t)(ab*TT + t))*1024 + 512 + h;
                    g_l[li]  = av;
                    g_lb[li] = __float2bfloat16(av);
                }
            }
            __syncthreads();
            if (tid == 0) red_add(&g_c2);
        }
        t1 += GRIDN; t2 += GRIDN;
    }
}

__global__ __launch_bounds__(256) void k_switch(
    const float* __restrict__ sw_W, const float* __restrict__ sw_b)
{
    int r = blockIdx.x*8 + (threadIdx.x >> 5);
    int lane = threadIdx.x & 31;
    const float4* l4 = (const float4*)(g_l + (size_t)r*1024);
    const float4* w4 = (const float4*)sw_W;
    float acc = 0.f;
    #pragma unroll
    for (int i = 0; i < 8; i++) {
        float4 a = l4[i*32 + lane], w = w4[i*32 + lane];
        acc = fmaf(a.x,w.x, fmaf(a.y,w.y, fmaf(a.z,w.z, fmaf(a.w,w.w, acc))));
    }
    #pragma unroll
    for (int o = 16; o; o >>= 1) acc += __shfl_xor_sync(0xffffffffu, acc, o);
    if (lane == 0) g_s[r] = sigf(acc + sw_b[0]);
}

__global__ __launch_bounds__(64) void k_ptr(
    const float* __restrict__ ents, const int* __restrict__ entlens,
    float* __restrict__ out, int write_tail)
{
    __shared__ float ds[HH];
    __shared__ float red[2];
    int r = blockIdx.x;
    int b = r >> 8;
    int tid = threadIdx.x;
    for (int i = tid; i < HH; i += 64) ds[i] = g_dec[(size_t)r*HH + i];
    __syncthreads();
    int len = entlens[b];
    float sv = -1e30f;
    if (tid <= len) {
        float acc = 0.f;
        const float4* e4 = (const float4*)(ents + (size_t)(b*NEN + tid)*HH);
        const float4* d4 = (const float4*)ds;
        #pragma unroll 8
        for (int i = 0; i < HH/4; i++) {
            float4 ev = e4[i], dv = d4[i];
            acc = fmaf(ev.x,dv.x, fmaf(ev.y,dv.y, fmaf(ev.z,dv.z, fmaf(ev.w,dv.w, acc))));
        }
        sv = acc;
    }
    float v = sv;
    #pragma unroll
    for (int o = 16; o; o >>= 1) v = fmaxf(v, __shfl_xor_sync(0xffffffffu, v, o));
    if ((tid & 31) == 0) red[tid >> 5] = v;
    __syncthreads();
    float m = fmaxf(red[0], red[1]);
    float e = (tid <= len) ? __expf(sv - m) : 0.f;
    float s2 = e;
    #pragma unroll
    for (int o = 16; o; o >>= 1) s2 += __shfl_xor_sync(0xffffffffu, s2, o);
    if ((tid & 31) == 0) red[tid >> 5] = s2;
    __syncthreads();
    float inv = 1.0f / (red[0] + red[1]);
    float s = g_s[r];
    float z = e * inv * (1.0f - s);
    out[(size_t)r*LDO + VOCAB + tid] = __logf(z + 1e-6f);
    if (write_tail) out[(size_t)NROWS*LDO + (size_t)r*NEN + tid] = z;
}

__global__ void k_rowc() {
    int r = blockIdx.x*256 + threadIdx.x;
    if (r < NROWS) g_c[r] = g_s[r] / g_rowsum[r];
}

__global__ __launch_bounds__(256) void k_final(float* __restrict__ out) {
    int r = blockIdx.x;
    float c = g_c[r];
    const __nv_bfloat162* src = (const __nv_bfloat162*)(g_logb + (size_t)r*VOCAB);
    float* dst = out + (size_t)r*LDO;
    for (int i = threadIdx.x; i < VOCAB/2; i += 256) {
        __nv_bfloat162 p = src[i];
        float2 o;
        o.x = __logf(fmaf(fexp(__bfloat162float(p.x)), c, 1e-6f));
        o.y = __logf(fmaf(fexp(__bfloat162float(p.y)), c, 1e-6f));
        *(float2*)&dst[i*2] = o;
    }
}

extern "C" void kernel_launch(void* const* d_in, const int* in_sizes, int n_in,
                              void* d_out, int out_size)
{
    const int*   outp    = (const int*)  d_in[0];
    const float* ents    = (const float*)d_in[1];
    const int*   entlens = (const int*)  d_in[2];
    const float* emb     = (const float*)d_in[3];
    const float* W_ih    = (const float*)d_in[4];
    const float* W_hh    = (const float*)d_in[5];
    const float* b_ih    = (const float*)d_in[6];
    const float* b_hh    = (const float*)d_in[7];
    const float* Wq      = (const float*)d_in[8];
    const float* Wk      = (const float*)d_in[9];
    const float* Wv      = (const float*)d_in[10];
    const float* out_W   = (const float*)d_in[11];
    const float* out_b   = (const float*)d_in[12];
    const float* sw_W    = (const float*)d_in[13];
    const float* sw_b    = (const float*)d_in[14];
    const float* mattn_W = (const float*)d_in[15];
    const float* mattn_b = (const float*)d_in[16];
    float* out = (float*)d_out;

    static int smem_set = 0;
    if (!smem_set) {
        cudaFuncSetAttribute(k_recur, cudaFuncAttributeMaxDynamicSharedMemorySize, 64*1024);
        smem_set = 1;
    }
    const int recur_smem = (8*1536 + 192) * 4;

    float *g_K_p, *g_V_p, *g_P_p, *g_Wqt_p, *g_l_p, *g_dec_p;
    cudaGetSymbolAddress((void**)&g_K_p, g_K);
    cudaGetSymbolAddress((void**)&g_V_p, g_V);
    cudaGetSymbolAddress((void**)&g_P_p, g_P);
    cudaGetSymbolAddress((void**)&g_Wqt_p, g_Wqt);
    cudaGetSymbolAddress((void**)&g_l_p, g_l);
    cudaGetSymbolAddress((void**)&g_dec_p, g_dec);

    k_init<<<12, 512>>>(ents);
    k_cvtw<<<VOCAB*1024/(256*4), 256>>>(out_W);
    k_transp<<<dim3(16,16), dim3(32,8)>>>(Wq);
    k_sgemm<<<dim3(4,4,1), 256>>>(ents, 512, 0, Wk, 512, 0, nullptr, g_K_p, 512, 0, 512);
    k_sgemm<<<dim3(4,4,1), 256>>>(ents, 512, 0, Wv, 512, 0, nullptr, g_V_p, 512, 0, 512);
    k_sgemm<<<dim3(4,4,4), 256>>>(g_K_p, 512, 128, g_Wqt_p, 512, 128, nullptr,
                                  g_P_p, 512, 512*512, 128);

    k_recur<<<GRIDN, 256, recur_smem>>>(W_ih, W_hh, b_ih, b_hh, emb, outp, entlens);

    k_switch<<<NROWS/8, 256>>>(sw_W, sw_b);
    k_sgemm<<<dim3(4,16,1), 256>>>(g_l_p, 1024, 0, mattn_W, 1024, 0, mattn_b,
                                   g_dec_p, 512, 0, 1024);
    k_logits_mma<<<dim3(VOCAB/128, NROWS/128), 256>>>(out_b);
    k_rowc<<<8, 256>>>();
    int write_tail = (out_size >= NROWS*LDO + NROWS*NEN) ? 1 : 0;
    k_ptr<<<NROWS, 64>>>(ents, entlens, out, write_tail);
    k_final<<<NROWS, 256>>>(out);
}